// round 2
// baseline (speedup 1.0000x reference)
#include <cuda_runtime.h>
#include <cuda_bf16.h>
#include <math.h>

// Problem constants
#define NN    4096
#define DD    2048
#define HH    8
#define DHH   256
#define HIDD  8192
#define EE    65536
#define LL    2
#define NC    751
#define SCALE 0.0625f   // 1/sqrt(256)

// ---------------- scratch (device globals; no allocation allowed) -------------
__device__ float g_x  [(size_t)NN * DD];
__device__ float g_q  [(size_t)NN * DD];
__device__ float g_k  [(size_t)NN * DD];
__device__ float g_v  [(size_t)NN * DD];
__device__ float g_agg[(size_t)NN * DD];
__device__ float g_tmp[(size_t)NN * DD];
__device__ float g_hid[(size_t)NN * HIDD];
__device__ float g_scores[(size_t)EE * HH];
__device__ int   g_deg [NN];
__device__ int   g_off [NN + 1];
__device__ int   g_fill[NN];
__device__ int   g_eidx[EE];

// ---------------- SGEMM: C[M,Nn] = A[M,K] @ B[K,Nn] + bias, optional ReLU -----
// 128x128 tile, BK=8, 256 threads, 8x8 per thread.
__global__ __launch_bounds__(256) void sgemm_kernel(
    const float* __restrict__ A, const float* __restrict__ B,
    const float* __restrict__ bias, float* __restrict__ C,
    int M, int Nn, int K, int relu)
{
    const int BM = 128, BN = 128, BK = 8, TM = 8, TN = 8;
    __shared__ float As[BK][BM];
    __shared__ float Bs[BK][BN];

    int tid = threadIdx.x;
    int bx = blockIdx.x, by = blockIdx.y;
    int tx = tid & 15, ty = tid >> 4;
    int rowBase = by * BM, colBase = bx * BN;

    int aRow = tid >> 1;          // 0..127
    int aCol = (tid & 1) * 4;     // 0 or 4
    int bRow = tid >> 5;          // 0..7
    int bCol = (tid & 31) * 4;    // 0..124

    float acc[TM][TN];
#pragma unroll
    for (int i = 0; i < TM; i++)
#pragma unroll
        for (int j = 0; j < TN; j++) acc[i][j] = 0.f;

    const bool nAligned = ((Nn & 3) == 0);

    for (int k0 = 0; k0 < K; k0 += BK) {
        // A tile (rows always in-bounds: M % 128 == 0, K % 8 == 0 here)
        float4 av = *(const float4*)(A + (size_t)(rowBase + aRow) * K + k0 + aCol);
        As[aCol + 0][aRow] = av.x;
        As[aCol + 1][aRow] = av.y;
        As[aCol + 2][aRow] = av.z;
        As[aCol + 3][aRow] = av.w;
        // B tile
        int bc = colBase + bCol;
        const float* Bp = B + (size_t)(k0 + bRow) * Nn;
        if (nAligned && bc + 3 < Nn) {
            float4 bv = *(const float4*)(Bp + bc);
            Bs[bRow][bCol + 0] = bv.x;
            Bs[bRow][bCol + 1] = bv.y;
            Bs[bRow][bCol + 2] = bv.z;
            Bs[bRow][bCol + 3] = bv.w;
        } else {
#pragma unroll
            for (int u = 0; u < 4; u++)
                Bs[bRow][bCol + u] = (bc + u < Nn) ? Bp[bc + u] : 0.f;
        }
        __syncthreads();

#pragma unroll
        for (int kk = 0; kk < BK; kk++) {
            float af[TM], bf[TN];
#pragma unroll
            for (int i = 0; i < TM; i++) af[i] = As[kk][ty * TM + i];
#pragma unroll
            for (int j = 0; j < TN; j++) bf[j] = Bs[kk][tx * TN + j];
#pragma unroll
            for (int i = 0; i < TM; i++)
#pragma unroll
                for (int j = 0; j < TN; j++)
                    acc[i][j] = fmaf(af[i], bf[j], acc[i][j]);
        }
        __syncthreads();
    }

#pragma unroll
    for (int i = 0; i < TM; i++) {
        int row = rowBase + ty * TM + i;
#pragma unroll
        for (int j = 0; j < TN; j++) {
            int col = colBase + tx * TN + j;
            if (col < Nn) {
                float vv = acc[i][j] + bias[col];
                if (relu) vv = fmaxf(vv, 0.f);
                C[(size_t)row * Nn + col] = vv;
            }
        }
    }
}

// ---------------- CSR build (group edges by destination c = ei[e][1]) --------
__global__ void k_zero(int* deg, int* fill) {
    int i = blockIdx.x * blockDim.x + threadIdx.x;
    if (i < NN) { deg[i] = 0; fill[i] = 0; }
}
__global__ void k_count(const int* __restrict__ ei, int* deg) {
    int e = blockIdx.x * blockDim.x + threadIdx.x;
    if (e < EE) atomicAdd(&deg[ei[2 * e + 1]], 1);
}
__global__ void k_scan(const int* __restrict__ deg, int* __restrict__ off) {
    __shared__ int s[NN];
    for (int i = threadIdx.x; i < NN; i += blockDim.x) s[i] = deg[i];
    __syncthreads();
    if (threadIdx.x == 0) {
        int acc = 0;
        for (int i = 0; i < NN; i++) { int d = s[i]; s[i] = acc; acc += d; }
    }
    __syncthreads();
    for (int i = threadIdx.x; i < NN; i += blockDim.x) off[i] = s[i];
    if (threadIdx.x == 0) off[NN] = EE;
}
__global__ void k_fill(const int* __restrict__ ei, const int* __restrict__ off,
                       int* fill, int* eidx) {
    int e = blockIdx.x * blockDim.x + threadIdx.x;
    if (e < EE) {
        int c = ei[2 * e + 1];
        int p = atomicAdd(&fill[c], 1);
        eidx[off[c] + p] = e;
    }
}

// ---------------- attention scores: per edge, per head dot(q[c], k[r]) -------
__global__ __launch_bounds__(256) void scores_kernel(
    const float* __restrict__ q, const float* __restrict__ k,
    const int* __restrict__ ei, float* __restrict__ scores)
{
    int e = blockIdx.x;
    int r = ei[2 * e], c = ei[2 * e + 1];
    int t = threadIdx.x;
    int h = t >> 5, lane = t & 31;
    const float* qp = q + (size_t)c * DD + h * DHH;
    const float* kp = k + (size_t)r * DD + h * DHH;
    float s = 0.f;
#pragma unroll
    for (int j = 0; j < 8; j++) {
        int d = lane + 32 * j;
        s = fmaf(qp[d], kp[d], s);
    }
#pragma unroll
    for (int o = 16; o; o >>= 1) s += __shfl_xor_sync(0xffffffffu, s, o);
    if (lane == 0) scores[(size_t)e * HH + h] = s * SCALE;
}

// ---------------- softmax + weighted aggregation per (node, head) ------------
__global__ __launch_bounds__(256) void attn_agg_kernel(
    const float* __restrict__ scores, const float* __restrict__ v,
    const int* __restrict__ ei, const int* __restrict__ off,
    const int* __restrict__ eidx, float* __restrict__ agg)
{
    int n = blockIdx.x, h = blockIdx.y;
    int t = threadIdx.x;   // 256 == DHH
    int beg = off[n], end = off[n + 1];
    __shared__ float sh[256];

    // max over incoming-edge scores
    float mx = -3.4e38f;
    for (int i = beg + t; i < end; i += 256)
        mx = fmaxf(mx, scores[(size_t)eidx[i] * HH + h]);
    sh[t] = mx; __syncthreads();
    for (int s2 = 128; s2; s2 >>= 1) {
        if (t < s2) sh[t] = fmaxf(sh[t], sh[t + s2]);
        __syncthreads();
    }
    float m = sh[0]; __syncthreads();

    // sum of exp
    float se = 0.f;
    for (int i = beg + t; i < end; i += 256)
        se += __expf(scores[(size_t)eidx[i] * HH + h] - m);
    sh[t] = se; __syncthreads();
    for (int s2 = 128; s2; s2 >>= 1) {
        if (t < s2) sh[t] += sh[t + s2];
        __syncthreads();
    }
    float den = sh[0];

    // aggregate: thread t owns dim d of this (n, h)
    float acc = 0.f;
    for (int i = beg; i < end; i++) {
        int e = eidx[i];
        int src = ei[2 * e];
        float w = __expf(scores[(size_t)e * HH + h] - m);
        acc = fmaf(w, v[(size_t)src * DD + h * DHH + t], acc);
    }
    agg[(size_t)n * DD + h * DHH + t] = (end > beg) ? (acc / den) : 0.f;
}

// ---------------- residual add + LayerNorm (in place on x) -------------------
__global__ __launch_bounds__(256) void add_ln_kernel(
    float* __restrict__ x, const float* __restrict__ x2,
    const float* __restrict__ g, const float* __restrict__ b)
{
    int n = blockIdx.x, t = threadIdx.x;
    size_t base = (size_t)n * DD;
    float loc[8];
    float s = 0.f, ss = 0.f;
#pragma unroll
    for (int j = 0; j < 8; j++) {
        int d = t + 256 * j;
        float vv = x[base + d] + x2[base + d];
        loc[j] = vv; s += vv; ss = fmaf(vv, vv, ss);
    }
    __shared__ float sh1[8], sh2[8];
#pragma unroll
    for (int o = 16; o; o >>= 1) {
        s  += __shfl_xor_sync(0xffffffffu, s, o);
        ss += __shfl_xor_sync(0xffffffffu, ss, o);
    }
    int w = t >> 5, lane = t & 31;
    if (lane == 0) { sh1[w] = s; sh2[w] = ss; }
    __syncthreads();
    if (t == 0) {
        float a = 0.f, c2 = 0.f;
        for (int i = 0; i < 8; i++) { a += sh1[i]; c2 += sh2[i]; }
        sh1[0] = a; sh2[0] = c2;
    }
    __syncthreads();
    float mean = sh1[0] * (1.0f / DD);
    float var  = sh2[0] * (1.0f / DD) - mean * mean;
    float inv  = rsqrtf(var + 1e-5f);
#pragma unroll
    for (int j = 0; j < 8; j++) {
        int d = t + 256 * j;
        x[base + d] = (loc[j] - mean) * inv * g[d] + b[d];
    }
}

// ---------------- host launcher ----------------------------------------------
extern "C" void kernel_launch(void* const* d_in, const int* in_sizes, int n_in,
                              void* d_out, int out_size)
{
    const float* feats = (const float*)d_in[0];
    const int*   ei    = (const int*)  d_in[1];
    const float* Wq  = (const float*)d_in[2];
    const float* bq  = (const float*)d_in[3];
    const float* Wk  = (const float*)d_in[4];
    const float* bk  = (const float*)d_in[5];
    const float* Wv  = (const float*)d_in[6];
    const float* bv  = (const float*)d_in[7];
    const float* Wo  = (const float*)d_in[8];
    const float* bo  = (const float*)d_in[9];
    const float* W1  = (const float*)d_in[10];
    const float* b1  = (const float*)d_in[11];
    const float* W2  = (const float*)d_in[12];
    const float* b2  = (const float*)d_in[13];
    const float* g1  = (const float*)d_in[14];
    const float* be1 = (const float*)d_in[15];
    const float* g2  = (const float*)d_in[16];
    const float* be2 = (const float*)d_in[17];
    const float* Wfc = (const float*)d_in[18];
    const float* bfc = (const float*)d_in[19];
    float* out = (float*)d_out;

    float *x, *q, *k, *v, *agg, *tmp, *hid, *scores;
    int *deg, *off, *fill, *eidx;
    cudaGetSymbolAddress((void**)&x,      g_x);
    cudaGetSymbolAddress((void**)&q,      g_q);
    cudaGetSymbolAddress((void**)&k,      g_k);
    cudaGetSymbolAddress((void**)&v,      g_v);
    cudaGetSymbolAddress((void**)&agg,    g_agg);
    cudaGetSymbolAddress((void**)&tmp,    g_tmp);
    cudaGetSymbolAddress((void**)&hid,    g_hid);
    cudaGetSymbolAddress((void**)&scores, g_scores);
    cudaGetSymbolAddress((void**)&deg,    g_deg);
    cudaGetSymbolAddress((void**)&off,    g_off);
    cudaGetSymbolAddress((void**)&fill,   g_fill);
    cudaGetSymbolAddress((void**)&eidx,   g_eidx);

    cudaMemcpyAsync(x, feats, (size_t)NN * DD * sizeof(float),
                    cudaMemcpyDeviceToDevice, 0);

    // CSR build (edges grouped by destination)
    k_zero <<<(NN + 255) / 256, 256>>>(deg, fill);
    k_count<<<(EE + 255) / 256, 256>>>(ei, deg);
    k_scan <<<1, 1024>>>(deg, off);
    k_fill <<<(EE + 255) / 256, 256>>>(ei, off, fill, eidx);

    dim3 gD((DD   + 127) / 128, NN / 128);
    dim3 gH((HIDD + 127) / 128, NN / 128);
    dim3 gF((NC   + 127) / 128, NN / 128);

    for (int i = 0; i < LL; i++) {
        size_t wOff = (size_t)i * DD * DD;
        sgemm_kernel<<<gD, 256>>>(x, Wq + wOff, bq + (size_t)i * DD, q,   NN, DD, DD, 0);
        sgemm_kernel<<<gD, 256>>>(x, Wk + wOff, bk + (size_t)i * DD, k,   NN, DD, DD, 0);
        sgemm_kernel<<<gD, 256>>>(x, Wv + wOff, bv + (size_t)i * DD, v,   NN, DD, DD, 0);

        scores_kernel<<<EE, 256>>>(q, k, ei, scores);
        attn_agg_kernel<<<dim3(NN, HH), 256>>>(scores, v, ei, off, eidx, agg);

        sgemm_kernel<<<gD, 256>>>(agg, Wo + wOff, bo + (size_t)i * DD, tmp, NN, DD, DD, 0);
        add_ln_kernel<<<NN, 256>>>(x, tmp, g1 + (size_t)i * DD, be1 + (size_t)i * DD);

        sgemm_kernel<<<gH, 256>>>(x,  W1 + (size_t)i * DD * HIDD, b1 + (size_t)i * HIDD,
                                  hid, NN, HIDD, DD, 1);
        sgemm_kernel<<<gD, 256>>>(hid, W2 + (size_t)i * HIDD * DD, b2 + (size_t)i * DD,
                                  tmp, NN, DD, HIDD, 0);
        add_ln_kernel<<<NN, 256>>>(x, tmp, g2 + (size_t)i * DD, be2 + (size_t)i * DD);
    }

    // logits -> first N*NC floats of out; then x -> remaining N*D floats
    sgemm_kernel<<<gF, 256>>>(x, Wfc, bfc, out, NN, NC, DD, 0);
    cudaMemcpyAsync(out + (size_t)NN * NC, x, (size_t)NN * DD * sizeof(float),
                    cudaMemcpyDeviceToDevice, 0);
}

// round 9
// speedup vs baseline: 2.8723x; 2.8723x over previous
#include <cuda_runtime.h>
#include <cuda_bf16.h>
#include <cstdint>
#include <math.h>

// Problem constants
#define NN    4096
#define DD    2048
#define HH    8
#define DHH   256
#define HIDD  8192
#define EE    65536
#define LL    2
#define NC    751
#define NCPAD 768
#define SCALE 0.0625f   // 1/sqrt(256)

// GEMM tiling (mma.sync path — works under plain sm_103 PTX target)
#define BMg 128
#define BNg 128
#define BKg 32
#define STAGES 3
#define STAGE_BYTES 32768          // Ah 8K | Al 8K | Bh 8K | Bl 8K
#define GEMM_SMEM (STAGES * STAGE_BYTES)

// ---------------- scratch (device globals; no allocation allowed) -------------
__device__ __align__(16) float g_x  [(size_t)NN * DD];
__device__ __align__(16) float g_q  [(size_t)NN * DD];
__device__ __align__(16) float g_k  [(size_t)NN * DD];
__device__ __align__(16) float g_v  [(size_t)NN * DD];
__device__ __align__(16) float g_agg[(size_t)NN * DD];
__device__ __align__(16) float g_tmp[(size_t)NN * DD];
__device__ __align__(16) float g_hid[(size_t)NN * HIDD];
__device__ __align__(16) float g_scores[(size_t)EE * HH];
__device__ int   g_deg [NN];
__device__ int   g_off [NN + 1];
__device__ int   g_fill[NN];
__device__ int   g_eidx[EE];

// Activation splits (sized for the largest: hid)
__device__ __align__(16) __nv_bfloat16 g_ah[(size_t)NN * HIDD];
__device__ __align__(16) __nv_bfloat16 g_al[(size_t)NN * HIDD];

// Transposed bf16 hi/lo weights ([N][K] layout per layer)
__device__ __align__(16) __nv_bfloat16 g_wqt_h[(size_t)LL * DD * DD];
__device__ __align__(16) __nv_bfloat16 g_wqt_l[(size_t)LL * DD * DD];
__device__ __align__(16) __nv_bfloat16 g_wkt_h[(size_t)LL * DD * DD];
__device__ __align__(16) __nv_bfloat16 g_wkt_l[(size_t)LL * DD * DD];
__device__ __align__(16) __nv_bfloat16 g_wvt_h[(size_t)LL * DD * DD];
__device__ __align__(16) __nv_bfloat16 g_wvt_l[(size_t)LL * DD * DD];
__device__ __align__(16) __nv_bfloat16 g_wot_h[(size_t)LL * DD * DD];
__device__ __align__(16) __nv_bfloat16 g_wot_l[(size_t)LL * DD * DD];
__device__ __align__(16) __nv_bfloat16 g_w1t_h[(size_t)LL * HIDD * DD];
__device__ __align__(16) __nv_bfloat16 g_w1t_l[(size_t)LL * HIDD * DD];
__device__ __align__(16) __nv_bfloat16 g_w2t_h[(size_t)LL * DD * HIDD];
__device__ __align__(16) __nv_bfloat16 g_w2t_l[(size_t)LL * DD * HIDD];
__device__ __align__(16) __nv_bfloat16 g_wfct_h[(size_t)NCPAD * DD];
__device__ __align__(16) __nv_bfloat16 g_wfct_l[(size_t)NCPAD * DD];

// ---------------- PTX helpers (sm_80-level only) ------------------------------
__device__ __forceinline__ uint32_t smem_u32(const void* p) {
    uint32_t a;
    asm("{ .reg .u64 t; cvta.to.shared.u64 t, %1; cvt.u32.u64 %0, t; }"
        : "=r"(a) : "l"(p));
    return a;
}
__device__ __forceinline__ void cp16(uint32_t s, const void* g) {
    asm volatile("cp.async.cg.shared.global [%0], [%1], 16;" :: "r"(s), "l"(g));
}
__device__ __forceinline__ void cp_commit() {
    asm volatile("cp.async.commit_group;" ::: "memory");
}
__device__ __forceinline__ void cp_wait1() {
    asm volatile("cp.async.wait_group 1;" ::: "memory");
}
__device__ __forceinline__ void ldsm4(uint32_t* r, uint32_t a) {
    asm volatile("ldmatrix.sync.aligned.m8n8.x4.shared.b16 {%0,%1,%2,%3}, [%4];"
                 : "=r"(r[0]), "=r"(r[1]), "=r"(r[2]), "=r"(r[3]) : "r"(a));
}
__device__ __forceinline__ void mma16816(float* d, const uint32_t* a, const uint32_t* b) {
    asm volatile("mma.sync.aligned.m16n8k16.row.col.f32.bf16.bf16.f32 "
                 "{%0,%1,%2,%3}, {%4,%5,%6,%7}, {%8,%9}, {%0,%1,%2,%3};"
                 : "+f"(d[0]), "+f"(d[1]), "+f"(d[2]), "+f"(d[3])
                 : "r"(a[0]), "r"(a[1]), "r"(a[2]), "r"(a[3]),
                   "r"(b[0]), "r"(b[1]));
}
// 64B rows, 4x16B chunks, XOR swizzle keeps ldmatrix reads conflict-free
__device__ __forceinline__ uint32_t tile_addr(uint32_t base, int row, int chunk) {
    return base + (uint32_t)(row * 64) + (uint32_t)((chunk ^ ((row >> 1) & 3)) * 16);
}

// ---------------- conversion kernels -----------------------------------------
__global__ void split_kernel(const float* __restrict__ X,
                             __nv_bfloat16* __restrict__ hi,
                             __nv_bfloat16* __restrict__ lo, size_t n) {
    size_t i = (size_t)blockIdx.x * blockDim.x + threadIdx.x;
    if (i < n) {
        float v = X[i];
        __nv_bfloat16 h = __float2bfloat16(v);
        hi[i] = h;
        lo[i] = __float2bfloat16(v - __bfloat162float(h));
    }
}

// W [K, Nn] fp32 row-major -> out [Npad, K] bf16 hi/lo (rows >= Nn zero-filled)
__global__ void transpose_split_kernel(const float* __restrict__ W,
                                       __nv_bfloat16* __restrict__ hi,
                                       __nv_bfloat16* __restrict__ lo,
                                       int K, int Nn, int Npad) {
    __shared__ float tile[32][33];
    int k0 = blockIdx.x * 32, n0 = blockIdx.y * 32;
    int tx = threadIdx.x, ty = threadIdx.y;   // 32 x 8
#pragma unroll
    for (int j = 0; j < 32; j += 8) {
        int k = k0 + ty + j, n = n0 + tx;
        tile[ty + j][tx] = (k < K && n < Nn) ? W[(size_t)k * Nn + n] : 0.f;
    }
    __syncthreads();
#pragma unroll
    for (int j = 0; j < 32; j += 8) {
        int n = n0 + ty + j, k = k0 + tx;
        if (n < Npad && k < K) {
            float v = tile[tx][ty + j];
            __nv_bfloat16 h = __float2bfloat16(v);
            hi[(size_t)n * K + k] = h;
            lo[(size_t)n * K + k] = __float2bfloat16(v - __bfloat162float(h));
        }
    }
}

// ---------------- bf16x3 GEMM on mma.sync (HMMA) ------------------------------
// C[M,Nn] = (Ah+Al)[M,K] @ (Bh+Bl)^T[Npad,K] + bias (+relu)
// grid = (Npad/128, M/128), 256 threads. 3-stage cp.async pipeline.
__global__ __launch_bounds__(256, 1) void bf16x3_gemm(
    const __nv_bfloat16* __restrict__ Ah, const __nv_bfloat16* __restrict__ Al,
    const __nv_bfloat16* __restrict__ Bh, const __nv_bfloat16* __restrict__ Bl,
    const float* __restrict__ bias, float* __restrict__ C,
    int K, int Nn, int relu)
{
    extern __shared__ char smem[];
    const uint32_t sb = smem_u32(smem);
    const int tid  = threadIdx.x;
    const int wid  = tid >> 5, lane = tid & 31;
    const int warpM = wid & 3;          // 4 warps along M (4*32 = 128)
    const int warpN = wid >> 2;         // 2 warps along N (2*64 = 128)
    const int g  = lane >> 3;           // ldmatrix address group
    const int lr = lane & 7;
    const size_t rowBase = (size_t)blockIdx.y * BMg;
    const size_t nBase   = (size_t)blockIdx.x * BNg;
    const int colBase    = blockIdx.x * BNg;
    const int nT = K / BKg;

    float acc[16][4];
#pragma unroll
    for (int i = 0; i < 16; i++)
#pragma unroll
        for (int j = 0; j < 4; j++) acc[i][j] = 0.f;

    // per-thread cp.async chunk pattern: 2048 16B chunks per stage
    // region 0: Ah, 1: Al, 2: Bh, 3: Bl ; within: row = idx>>2, chunk = idx&3
    auto load_stage = [&](int stage, int kt) {
        const uint32_t st = sb + stage * STAGE_BYTES;
        const int k0 = kt * BKg;
#pragma unroll
        for (int i = 0; i < 8; i++) {
            int c = tid + i * 256;
            int region = c >> 9;
            int idx = c & 511;
            int row = idx >> 2, ch = idx & 3;
            uint32_t soff = (uint32_t)region * 8192u
                          + (uint32_t)(row * 64)
                          + (uint32_t)((ch ^ ((row >> 1) & 3)) * 16);
            const __nv_bfloat16* gp;
            if (region == 0)      gp = Ah + (rowBase + row) * (size_t)K + k0 + ch * 8;
            else if (region == 1) gp = Al + (rowBase + row) * (size_t)K + k0 + ch * 8;
            else if (region == 2) gp = Bh + (nBase + row) * (size_t)K + k0 + ch * 8;
            else                  gp = Bl + (nBase + row) * (size_t)K + k0 + ch * 8;
            cp16(st + soff, gp);
        }
    };

    // prologue: stages 0 and 1
    load_stage(0, 0); cp_commit();
    load_stage(1, 1); cp_commit();

    const int mOff = warpM * 32;
    const int nOff = warpN * 64;

    for (int kt = 0; kt < nT; kt++) {
        cp_wait1();            // stage kt data arrived
        __syncthreads();       // visible to all warps; prior compute done
        if (kt + 2 < nT) load_stage((kt + 2) % STAGES, kt + 2);
        cp_commit();           // always commit to keep group numbering

        const uint32_t st = sb + (kt % STAGES) * STAGE_BYTES;
        const uint32_t aB  = st;
        const uint32_t alB = st + 8192;
        const uint32_t bB  = st + 16384;
        const uint32_t blB = st + 24576;

#pragma unroll
        for (int ks = 0; ks < 2; ks++) {
            uint32_t ah[2][4], alr[2][4], bh[4][4], bl[4][4];
#pragma unroll
            for (int mt = 0; mt < 2; mt++) {
                int r = mOff + mt * 16 + lr + (g & 1) * 8;
                int ch = 2 * ks + (g >> 1);
                ldsm4(ah[mt],  tile_addr(aB,  r, ch));
                ldsm4(alr[mt], tile_addr(alB, r, ch));
            }
#pragma unroll
            for (int p = 0; p < 4; p++) {
                int r = nOff + p * 16 + lr + (g >> 1) * 8;
                int ch = 2 * ks + (g & 1);
                ldsm4(bh[p], tile_addr(bB,  r, ch));
                ldsm4(bl[p], tile_addr(blB, r, ch));
            }
#pragma unroll
            for (int mt = 0; mt < 2; mt++)
#pragma unroll
                for (int nt = 0; nt < 8; nt++) {
                    float* d = acc[mt * 8 + nt];
                    const uint32_t* bhp = &bh[nt >> 1][(nt & 1) * 2];
                    const uint32_t* blp = &bl[nt >> 1][(nt & 1) * 2];
                    mma16816(d, ah[mt],  bhp);
                    mma16816(d, alr[mt], bhp);
                    mma16816(d, ah[mt],  blp);
                }
        }
    }

    // epilogue: direct stores (fragment: row = lane>>2 (+8), cols 2*(lane&3) (+1))
#pragma unroll
    for (int mt = 0; mt < 2; mt++)
#pragma unroll
        for (int nt = 0; nt < 8; nt++) {
            const float* d = acc[mt * 8 + nt];
            size_t row0 = rowBase + mOff + mt * 16 + (lane >> 2);
            int col0 = colBase + nOff + nt * 8 + (lane & 3) * 2;
            if (col0 < Nn) {
                float v0 = d[0] + bias[col0];
                float v2 = d[2] + bias[col0];
                if (relu) { v0 = fmaxf(v0, 0.f); v2 = fmaxf(v2, 0.f); }
                C[row0 * (size_t)Nn + col0]       = v0;
                C[(row0 + 8) * (size_t)Nn + col0] = v2;
            }
            if (col0 + 1 < Nn) {
                float v1 = d[1] + bias[col0 + 1];
                float v3 = d[3] + bias[col0 + 1];
                if (relu) { v1 = fmaxf(v1, 0.f); v3 = fmaxf(v3, 0.f); }
                C[row0 * (size_t)Nn + col0 + 1]       = v1;
                C[(row0 + 8) * (size_t)Nn + col0 + 1] = v3;
            }
        }
}

// ---------------- CSR build (group edges by destination c = ei[e][1]) --------
__global__ void k_zero(int* deg, int* fill) {
    int i = blockIdx.x * blockDim.x + threadIdx.x;
    if (i < NN) { deg[i] = 0; fill[i] = 0; }
}
__global__ void k_count(const int* __restrict__ ei, int* deg) {
    int e = blockIdx.x * blockDim.x + threadIdx.x;
    if (e < EE) atomicAdd(&deg[ei[2 * e + 1]], 1);
}
__global__ void k_scan(const int* __restrict__ deg, int* __restrict__ off) {
    __shared__ int s[NN];
    for (int i = threadIdx.x; i < NN; i += blockDim.x) s[i] = deg[i];
    __syncthreads();
    if (threadIdx.x == 0) {
        int acc = 0;
        for (int i = 0; i < NN; i++) { int d = s[i]; s[i] = acc; acc += d; }
    }
    __syncthreads();
    for (int i = threadIdx.x; i < NN; i += blockDim.x) off[i] = s[i];
    if (threadIdx.x == 0) off[NN] = EE;
}
__global__ void k_fill(const int* __restrict__ ei, const int* __restrict__ off,
                       int* fill, int* eidx) {
    int e = blockIdx.x * blockDim.x + threadIdx.x;
    if (e < EE) {
        int c = ei[2 * e + 1];
        int p = atomicAdd(&fill[c], 1);
        eidx[off[c] + p] = e;
    }
}

// ---------------- attention scores: per edge, per head dot(q[c], k[r]) -------
__global__ __launch_bounds__(256) void scores_kernel(
    const float* __restrict__ q, const float* __restrict__ k,
    const int* __restrict__ ei, float* __restrict__ scores)
{
    int e = blockIdx.x;
    int r = ei[2 * e], c = ei[2 * e + 1];
    int t = threadIdx.x;
    int h = t >> 5, lane = t & 31;
    const float* qp = q + (size_t)c * DD + h * DHH;
    const float* kp = k + (size_t)r * DD + h * DHH;
    float s = 0.f;
#pragma unroll
    for (int j = 0; j < 8; j++) {
        int d = lane + 32 * j;
        s = fmaf(qp[d], kp[d], s);
    }
#pragma unroll
    for (int o = 16; o; o >>= 1) s += __shfl_xor_sync(0xffffffffu, s, o);
    if (lane == 0) scores[(size_t)e * HH + h] = s * SCALE;
}

// ---------------- softmax + weighted aggregation per (node, head) ------------
__global__ __launch_bounds__(256) void attn_agg_kernel(
    const float* __restrict__ scores, const float* __restrict__ v,
    const int* __restrict__ ei, const int* __restrict__ off,
    const int* __restrict__ eidx, float* __restrict__ agg)
{
    int n = blockIdx.x, h = blockIdx.y;
    int t = threadIdx.x;   // 256 == DHH
    int beg = off[n], end = off[n + 1];
    __shared__ float sh[256];

    float mx = -3.4e38f;
    for (int i = beg + t; i < end; i += 256)
        mx = fmaxf(mx, scores[(size_t)eidx[i] * HH + h]);
    sh[t] = mx; __syncthreads();
    for (int s2 = 128; s2; s2 >>= 1) {
        if (t < s2) sh[t] = fmaxf(sh[t], sh[t + s2]);
        __syncthreads();
    }
    float m = sh[0]; __syncthreads();

    float se = 0.f;
    for (int i = beg + t; i < end; i += 256)
        se += __expf(scores[(size_t)eidx[i] * HH + h] - m);
    sh[t] = se; __syncthreads();
    for (int s2 = 128; s2; s2 >>= 1) {
        if (t < s2) sh[t] += sh[t + s2];
        __syncthreads();
    }
    float den = sh[0];

    float acc = 0.f;
    for (int i = beg; i < end; i++) {
        int e = eidx[i];
        int src = ei[2 * e];
        float w = __expf(scores[(size_t)e * HH + h] - m);
        acc = fmaf(w, v[(size_t)src * DD + h * DHH + t], acc);
    }
    agg[(size_t)n * DD + h * DHH + t] = (end > beg) ? (acc / den) : 0.f;
}

// ---------------- residual add + LayerNorm (in place on x) -------------------
__global__ __launch_bounds__(256) void add_ln_kernel(
    float* __restrict__ x, const float* __restrict__ x2,
    const float* __restrict__ g, const float* __restrict__ b)
{
    int n = blockIdx.x, t = threadIdx.x;
    size_t base = (size_t)n * DD;
    float loc[8];
    float s = 0.f, ss = 0.f;
#pragma unroll
    for (int j = 0; j < 8; j++) {
        int d = t + 256 * j;
        float vv = x[base + d] + x2[base + d];
        loc[j] = vv; s += vv; ss = fmaf(vv, vv, ss);
    }
    __shared__ float sh1[8], sh2[8];
#pragma unroll
    for (int o = 16; o; o >>= 1) {
        s  += __shfl_xor_sync(0xffffffffu, s, o);
        ss += __shfl_xor_sync(0xffffffffu, ss, o);
    }
    int w = t >> 5, lane = t & 31;
    if (lane == 0) { sh1[w] = s; sh2[w] = ss; }
    __syncthreads();
    if (t == 0) {
        float a = 0.f, c2 = 0.f;
        for (int i = 0; i < 8; i++) { a += sh1[i]; c2 += sh2[i]; }
        sh1[0] = a; sh2[0] = c2;
    }
    __syncthreads();
    float mean = sh1[0] * (1.0f / DD);
    float var  = sh2[0] * (1.0f / DD) - mean * mean;
    float inv  = rsqrtf(var + 1e-5f);
#pragma unroll
    for (int j = 0; j < 8; j++) {
        int d = t + 256 * j;
        x[base + d] = (loc[j] - mean) * inv * g[d] + b[d];
    }
}

// ---------------- host launcher ----------------------------------------------
extern "C" void kernel_launch(void* const* d_in, const int* in_sizes, int n_in,
                              void* d_out, int out_size)
{
    const float* feats = (const float*)d_in[0];
    const int*   ei    = (const int*)  d_in[1];
    const float* Wq  = (const float*)d_in[2];
    const float* bq  = (const float*)d_in[3];
    const float* Wk  = (const float*)d_in[4];
    const float* bk  = (const float*)d_in[5];
    const float* Wv  = (const float*)d_in[6];
    const float* bv  = (const float*)d_in[7];
    const float* Wo  = (const float*)d_in[8];
    const float* bo  = (const float*)d_in[9];
    const float* W1  = (const float*)d_in[10];
    const float* b1  = (const float*)d_in[11];
    const float* W2  = (const float*)d_in[12];
    const float* b2  = (const float*)d_in[13];
    const float* g1  = (const float*)d_in[14];
    const float* be1 = (const float*)d_in[15];
    const float* g2  = (const float*)d_in[16];
    const float* be2 = (const float*)d_in[17];
    const float* Wfc = (const float*)d_in[18];
    const float* bfc = (const float*)d_in[19];
    float* out = (float*)d_out;

    float *x, *q, *k, *v, *agg, *tmp, *hid, *scores;
    int *deg, *off, *fill, *eidx;
    __nv_bfloat16 *ah, *al;
    __nv_bfloat16 *wqh, *wql, *wkh, *wkl, *wvh, *wvl, *woh, *wol;
    __nv_bfloat16 *w1h, *w1l, *w2h, *w2l, *wfh, *wfl;

    cudaGetSymbolAddress((void**)&x,      g_x);
    cudaGetSymbolAddress((void**)&q,      g_q);
    cudaGetSymbolAddress((void**)&k,      g_k);
    cudaGetSymbolAddress((void**)&v,      g_v);
    cudaGetSymbolAddress((void**)&agg,    g_agg);
    cudaGetSymbolAddress((void**)&tmp,    g_tmp);
    cudaGetSymbolAddress((void**)&hid,    g_hid);
    cudaGetSymbolAddress((void**)&scores, g_scores);
    cudaGetSymbolAddress((void**)&deg,    g_deg);
    cudaGetSymbolAddress((void**)&off,    g_off);
    cudaGetSymbolAddress((void**)&fill,   g_fill);
    cudaGetSymbolAddress((void**)&eidx,   g_eidx);
    cudaGetSymbolAddress((void**)&ah,     g_ah);
    cudaGetSymbolAddress((void**)&al,     g_al);
    cudaGetSymbolAddress((void**)&wqh,    g_wqt_h);
    cudaGetSymbolAddress((void**)&wql,    g_wqt_l);
    cudaGetSymbolAddress((void**)&wkh,    g_wkt_h);
    cudaGetSymbolAddress((void**)&wkl,    g_wkt_l);
    cudaGetSymbolAddress((void**)&wvh,    g_wvt_h);
    cudaGetSymbolAddress((void**)&wvl,    g_wvt_l);
    cudaGetSymbolAddress((void**)&woh,    g_wot_h);
    cudaGetSymbolAddress((void**)&wol,    g_wot_l);
    cudaGetSymbolAddress((void**)&w1h,    g_w1t_h);
    cudaGetSymbolAddress((void**)&w1l,    g_w1t_l);
    cudaGetSymbolAddress((void**)&w2h,    g_w2t_h);
    cudaGetSymbolAddress((void**)&w2l,    g_w2t_l);
    cudaGetSymbolAddress((void**)&wfh,    g_wfct_h);
    cudaGetSymbolAddress((void**)&wfl,    g_wfct_l);

    cudaFuncSetAttribute(bf16x3_gemm,
                         cudaFuncAttributeMaxDynamicSharedMemorySize, GEMM_SMEM);

    cudaMemcpyAsync(x, feats, (size_t)NN * DD * sizeof(float),
                    cudaMemcpyDeviceToDevice, 0);

    // CSR build
    k_zero <<<(NN + 255) / 256, 256>>>(deg, fill);
    k_count<<<(EE + 255) / 256, 256>>>(ei, deg);
    k_scan <<<1, 1024>>>(deg, off);
    k_fill <<<(EE + 255) / 256, 256>>>(ei, off, fill, eidx);

    // Weight conversion (transpose + bf16 hi/lo split)
    dim3 tsb(32, 8);
    for (int i = 0; i < LL; i++) {
        size_t oD = (size_t)i * DD * DD, oH = (size_t)i * DD * HIDD;
        transpose_split_kernel<<<dim3(64, 64),  tsb>>>(Wq + oD, wqh + oD, wql + oD, DD, DD, DD);
        transpose_split_kernel<<<dim3(64, 64),  tsb>>>(Wk + oD, wkh + oD, wkl + oD, DD, DD, DD);
        transpose_split_kernel<<<dim3(64, 64),  tsb>>>(Wv + oD, wvh + oD, wvl + oD, DD, DD, DD);
        transpose_split_kernel<<<dim3(64, 64),  tsb>>>(Wo + oD, woh + oD, wol + oD, DD, DD, DD);
        transpose_split_kernel<<<dim3(64, 256), tsb>>>(W1 + oH, w1h + oH, w1l + oH, DD, HIDD, HIDD);
        transpose_split_kernel<<<dim3(256, 64), tsb>>>(W2 + oH, w2h + oH, w2l + oH, HIDD, DD, DD);
    }
    transpose_split_kernel<<<dim3(64, 24), tsb>>>(Wfc, wfh, wfl, DD, NC, NCPAD);

    const size_t nXD = (size_t)NN * DD;
    const size_t nXH = (size_t)NN * HIDD;
    dim3 gD(DD / BNg,    NN / BMg);   // (16, 32)
    dim3 gH(HIDD / BNg,  NN / BMg);   // (64, 32)
    dim3 gF(NCPAD / BNg, NN / BMg);   // (6, 32)

    for (int i = 0; i < LL; i++) {
        size_t oD = (size_t)i * DD * DD, oH = (size_t)i * DD * HIDD;
        const float* bqi = bq + (size_t)i * DD;
        const float* bki = bk + (size_t)i * DD;
        const float* bvi = bv + (size_t)i * DD;
        const float* boi = bo + (size_t)i * DD;

        split_kernel<<<(unsigned)((nXD + 255) / 256), 256>>>(x, ah, al, nXD);
        bf16x3_gemm<<<gD, 256, GEMM_SMEM>>>(ah, al, wqh + oD, wql + oD, bqi, q, DD, DD, 0);
        bf16x3_gemm<<<gD, 256, GEMM_SMEM>>>(ah, al, wkh + oD, wkl + oD, bki, k, DD, DD, 0);
        bf16x3_gemm<<<gD, 256, GEMM_SMEM>>>(ah, al, wvh + oD, wvl + oD, bvi, v, DD, DD, 0);

        scores_kernel<<<EE, 256>>>(q, k, ei, scores);
        attn_agg_kernel<<<dim3(NN, HH), 256>>>(scores, v, ei, off, eidx, agg);

        split_kernel<<<(unsigned)((nXD + 255) / 256), 256>>>(agg, ah, al, nXD);
        bf16x3_gemm<<<gD, 256, GEMM_SMEM>>>(ah, al, woh + oD, wol + oD, boi, tmp, DD, DD, 0);
        add_ln_kernel<<<NN, 256>>>(x, tmp, g1 + (size_t)i * DD, be1 + (size_t)i * DD);

        split_kernel<<<(unsigned)((nXD + 255) / 256), 256>>>(x, ah, al, nXD);
        bf16x3_gemm<<<gH, 256, GEMM_SMEM>>>(ah, al, w1h + oH, w1l + oH,
                                            b1 + (size_t)i * HIDD, hid, DD, HIDD, 1);

        split_kernel<<<(unsigned)((nXH + 255) / 256), 256>>>(hid, ah, al, nXH);
        bf16x3_gemm<<<gD, 256, GEMM_SMEM>>>(ah, al, w2h + oH, w2l + oH,
                                            b2 + (size_t)i * DD, tmp, HIDD, DD, 0);
        add_ln_kernel<<<NN, 256>>>(x, tmp, g2 + (size_t)i * DD, be2 + (size_t)i * DD);
    }

    // logits -> first N*NC floats; then x -> remaining N*D floats
    split_kernel<<<(unsigned)((nXD + 255) / 256), 256>>>(x, ah, al, nXD);
    bf16x3_gemm<<<gF, 256, GEMM_SMEM>>>(ah, al, wfh, wfl, bfc, out, DD, NC, 0);
    cudaMemcpyAsync(out + (size_t)NN * NC, x, (size_t)NN * DD * sizeof(float),
                    cudaMemcpyDeviceToDevice, 0);
}

// round 10
// speedup vs baseline: 3.0404x; 1.0585x over previous
#include <cuda_runtime.h>
#include <cuda_bf16.h>
#include <cstdint>
#include <math.h>

// Problem constants
#define NN    4096
#define DD    2048
#define HH    8
#define DHH   256
#define HIDD  8192
#define EE    65536
#define LL    2
#define NC    751
#define NCPAD 768
#define SCALE 0.0625f   // 1/sqrt(256)

// GEMM tiling (mma.sync path — works under plain sm_103 PTX target)
#define BMg 256
#define BNg 128
#define BKg 32
#define STAGES 3
#define STAGE_BYTES 49152          // Ah 16K | Al 16K | Bh 8K | Bl 8K
#define GEMM_SMEM (STAGES * STAGE_BYTES)
#define GEMM_THREADS 512

// ---------------- scratch (device globals; no allocation allowed) -------------
__device__ __align__(16) float g_x  [(size_t)NN * DD];
__device__ __align__(16) float g_q  [(size_t)NN * DD];
__device__ __align__(16) float g_k  [(size_t)NN * DD];
__device__ __align__(16) float g_v  [(size_t)NN * DD];
__device__ __align__(16) float g_tmp[(size_t)NN * DD];
__device__ __align__(16) float g_scores[(size_t)EE * HH];
__device__ int   g_deg [NN];
__device__ int   g_off [NN + 1];
__device__ int   g_fill[NN];
__device__ int   g_eidx[EE];

// bf16 hi/lo splits of activations
__device__ __align__(16) __nv_bfloat16 g_xh[(size_t)NN * DD];
__device__ __align__(16) __nv_bfloat16 g_xl[(size_t)NN * DD];
__device__ __align__(16) __nv_bfloat16 g_hh[(size_t)NN * HIDD];
__device__ __align__(16) __nv_bfloat16 g_hl[(size_t)NN * HIDD];

// Transposed bf16 hi/lo weights ([N][K] layout per layer)
__device__ __align__(16) __nv_bfloat16 g_wqt_h[(size_t)LL * DD * DD];
__device__ __align__(16) __nv_bfloat16 g_wqt_l[(size_t)LL * DD * DD];
__device__ __align__(16) __nv_bfloat16 g_wkt_h[(size_t)LL * DD * DD];
__device__ __align__(16) __nv_bfloat16 g_wkt_l[(size_t)LL * DD * DD];
__device__ __align__(16) __nv_bfloat16 g_wvt_h[(size_t)LL * DD * DD];
__device__ __align__(16) __nv_bfloat16 g_wvt_l[(size_t)LL * DD * DD];
__device__ __align__(16) __nv_bfloat16 g_wot_h[(size_t)LL * DD * DD];
__device__ __align__(16) __nv_bfloat16 g_wot_l[(size_t)LL * DD * DD];
__device__ __align__(16) __nv_bfloat16 g_w1t_h[(size_t)LL * HIDD * DD];
__device__ __align__(16) __nv_bfloat16 g_w1t_l[(size_t)LL * HIDD * DD];
__device__ __align__(16) __nv_bfloat16 g_w2t_h[(size_t)LL * DD * HIDD];
__device__ __align__(16) __nv_bfloat16 g_w2t_l[(size_t)LL * DD * HIDD];
__device__ __align__(16) __nv_bfloat16 g_wfct_h[(size_t)NCPAD * DD];
__device__ __align__(16) __nv_bfloat16 g_wfct_l[(size_t)NCPAD * DD];

// ---------------- PTX helpers (sm_80-level only) ------------------------------
__device__ __forceinline__ uint32_t smem_u32(const void* p) {
    uint32_t a;
    asm("{ .reg .u64 t; cvta.to.shared.u64 t, %1; cvt.u32.u64 %0, t; }"
        : "=r"(a) : "l"(p));
    return a;
}
__device__ __forceinline__ void cp16(uint32_t s, const void* g) {
    asm volatile("cp.async.cg.shared.global [%0], [%1], 16;" :: "r"(s), "l"(g));
}
__device__ __forceinline__ void cp_commit() {
    asm volatile("cp.async.commit_group;" ::: "memory");
}
__device__ __forceinline__ void cp_wait1() {
    asm volatile("cp.async.wait_group 1;" ::: "memory");
}
__device__ __forceinline__ void ldsm4(uint32_t* r, uint32_t a) {
    asm volatile("ldmatrix.sync.aligned.m8n8.x4.shared.b16 {%0,%1,%2,%3}, [%4];"
                 : "=r"(r[0]), "=r"(r[1]), "=r"(r[2]), "=r"(r[3]) : "r"(a));
}
__device__ __forceinline__ void mma16816(float* d, const uint32_t* a, const uint32_t* b) {
    asm volatile("mma.sync.aligned.m16n8k16.row.col.f32.bf16.bf16.f32 "
                 "{%0,%1,%2,%3}, {%4,%5,%6,%7}, {%8,%9}, {%0,%1,%2,%3};"
                 : "+f"(d[0]), "+f"(d[1]), "+f"(d[2]), "+f"(d[3])
                 : "r"(a[0]), "r"(a[1]), "r"(a[2]), "r"(a[3]),
                   "r"(b[0]), "r"(b[1]));
}
// 64B rows, 4x16B chunks, XOR swizzle keeps ldmatrix reads conflict-free
__device__ __forceinline__ uint32_t tile_addr(uint32_t base, int row, int chunk) {
    return base + (uint32_t)(row * 64) + (uint32_t)((chunk ^ ((row >> 1) & 3)) * 16);
}
__device__ __forceinline__ void split_write(__nv_bfloat16* hi, __nv_bfloat16* lo,
                                            size_t idx, float v) {
    __nv_bfloat16 h = __float2bfloat16(v);
    hi[idx] = h;
    lo[idx] = __float2bfloat16(v - __bfloat162float(h));
}

// ---------------- conversion kernels -----------------------------------------
__global__ void split_kernel(const float* __restrict__ X,
                             __nv_bfloat16* __restrict__ hi,
                             __nv_bfloat16* __restrict__ lo, size_t n) {
    size_t i = (size_t)blockIdx.x * blockDim.x + threadIdx.x;
    if (i < n) split_write(hi, lo, i, X[i]);
}

// W [K, Nn] fp32 row-major -> out [Npad, K] bf16 hi/lo (rows >= Nn zero-filled)
__global__ void transpose_split_kernel(const float* __restrict__ W,
                                       __nv_bfloat16* __restrict__ hi,
                                       __nv_bfloat16* __restrict__ lo,
                                       int K, int Nn, int Npad) {
    __shared__ float tile[32][33];
    int k0 = blockIdx.x * 32, n0 = blockIdx.y * 32;
    int tx = threadIdx.x, ty = threadIdx.y;   // 32 x 8
#pragma unroll
    for (int j = 0; j < 32; j += 8) {
        int k = k0 + ty + j, n = n0 + tx;
        tile[ty + j][tx] = (k < K && n < Nn) ? W[(size_t)k * Nn + n] : 0.f;
    }
    __syncthreads();
#pragma unroll
    for (int j = 0; j < 32; j += 8) {
        int n = n0 + ty + j, k = k0 + tx;
        if (n < Npad && k < K) {
            float v = tile[tx][ty + j];
            __nv_bfloat16 h = __float2bfloat16(v);
            hi[(size_t)n * K + k] = h;
            lo[(size_t)n * K + k] = __float2bfloat16(v - __bfloat162float(h));
        }
    }
}

// ---------------- bf16x3 GEMM on mma.sync (HMMA) ------------------------------
// C = (Ah+Al)[M,K] @ (Bh+Bl)^T[Npad,K] + bias
// mode 0: fp32 C; mode 2: relu + bf16 hi/lo split outputs (Ch/Cl)
// grid = (Npad/128, M/256), 512 threads. 3-stage cp.async pipeline.
__global__ __launch_bounds__(GEMM_THREADS, 1) void bf16x3_gemm(
    const __nv_bfloat16* __restrict__ Ah, const __nv_bfloat16* __restrict__ Al,
    const __nv_bfloat16* __restrict__ Bh, const __nv_bfloat16* __restrict__ Bl,
    const float* __restrict__ bias, float* __restrict__ C,
    __nv_bfloat16* __restrict__ Ch, __nv_bfloat16* __restrict__ Cl,
    int K, int Nn, int mode)
{
    extern __shared__ char smem[];
    const uint32_t sb = smem_u32(smem);
    const int tid  = threadIdx.x;
    const int wid  = tid >> 5, lane = tid & 31;
    const int warpM = wid & 7;          // 8 warps along M (8*32 = 256)
    const int warpN = wid >> 3;         // 2 warps along N (2*64 = 128)
    const int g  = lane >> 3;           // ldmatrix address group
    const int lr = lane & 7;
    const size_t rowBase = (size_t)blockIdx.y * BMg;
    const size_t nBase   = (size_t)blockIdx.x * BNg;
    const int colBase    = blockIdx.x * BNg;
    const int nT = K / BKg;

    float acc[16][4];
#pragma unroll
    for (int i = 0; i < 16; i++)
#pragma unroll
        for (int j = 0; j < 4; j++) acc[i][j] = 0.f;

    // per-stage: 3072 16B chunks (Ah 1024 | Al 1024 | Bh 512 | Bl 512), 6/thread
    auto load_stage = [&](int stage, int kt) {
        const uint32_t st = sb + stage * STAGE_BYTES;
        const int k0 = kt * BKg;
#pragma unroll
        for (int i = 0; i < 6; i++) {
            int c = tid + i * GEMM_THREADS;
            uint32_t soff;
            const __nv_bfloat16* gp;
            if (c < 2048) {
                int reg = c >> 10;
                int idx = c & 1023;
                int row = idx >> 2, ch = idx & 3;
                soff = (uint32_t)reg * 16384u + (uint32_t)(row * 64)
                     + (uint32_t)((ch ^ ((row >> 1) & 3)) * 16);
                gp = (reg ? Al : Ah) + (rowBase + row) * (size_t)K + k0 + ch * 8;
            } else {
                int c2 = c - 2048;
                int reg = c2 >> 9;
                int idx = c2 & 511;
                int row = idx >> 2, ch = idx & 3;
                soff = 32768u + (uint32_t)reg * 8192u + (uint32_t)(row * 64)
                     + (uint32_t)((ch ^ ((row >> 1) & 3)) * 16);
                gp = (reg ? Bl : Bh) + (nBase + row) * (size_t)K + k0 + ch * 8;
            }
            cp16(st + soff, gp);
        }
    };

    // prologue: stages 0 and 1
    load_stage(0, 0); cp_commit();
    load_stage(1, 1); cp_commit();

    const int mOff = warpM * 32;
    const int nOff = warpN * 64;

    for (int kt = 0; kt < nT; kt++) {
        cp_wait1();            // stage kt data arrived
        __syncthreads();       // visible to all warps; prior compute done
        if (kt + 2 < nT) load_stage((kt + 2) % STAGES, kt + 2);
        cp_commit();           // always commit to keep group numbering

        const uint32_t st = sb + (kt % STAGES) * STAGE_BYTES;
        const uint32_t aB  = st;
        const uint32_t alB = st + 16384;
        const uint32_t bB  = st + 32768;
        const uint32_t blB = st + 40960;

#pragma unroll
        for (int ks = 0; ks < 2; ks++) {
            uint32_t ahf[2][4], alf[2][4];
#pragma unroll
            for (int mt = 0; mt < 2; mt++) {
                int r = mOff + mt * 16 + lr + (g & 1) * 8;
                int ch = 2 * ks + (g >> 1);
                ldsm4(ahf[mt], tile_addr(aB,  r, ch));
                ldsm4(alf[mt], tile_addr(alB, r, ch));
            }
#pragma unroll
            for (int p = 0; p < 4; p++) {
                uint32_t bh[4], bl[4];
                int r = nOff + p * 16 + lr + (g >> 1) * 8;
                int ch = 2 * ks + (g & 1);
                ldsm4(bh, tile_addr(bB,  r, ch));
                ldsm4(bl, tile_addr(blB, r, ch));
#pragma unroll
                for (int mt = 0; mt < 2; mt++) {
                    float* d0 = acc[mt * 8 + 2 * p];
                    float* d1 = acc[mt * 8 + 2 * p + 1];
                    mma16816(d0, ahf[mt], bh);
                    mma16816(d0, alf[mt], bh);
                    mma16816(d0, ahf[mt], bl);
                    mma16816(d1, ahf[mt], bh + 2);
                    mma16816(d1, alf[mt], bh + 2);
                    mma16816(d1, ahf[mt], bl + 2);
                }
            }
        }
    }

    // epilogue (fragment: rows lane>>2, +8; cols 2*(lane&3), +1)
#pragma unroll
    for (int mt = 0; mt < 2; mt++)
#pragma unroll
        for (int nt = 0; nt < 8; nt++) {
            const float* d = acc[mt * 8 + nt];
            size_t row0 = rowBase + mOff + mt * 16 + (lane >> 2);
            int col0 = colBase + nOff + nt * 8 + (lane & 3) * 2;
            if (col0 >= Nn) continue;
            float b0 = bias[col0];
            float b1 = (col0 + 1 < Nn) ? bias[col0 + 1] : 0.f;
            float v0 = d[0] + b0, v1 = d[1] + b1;
            float v2 = d[2] + b0, v3 = d[3] + b1;
            if (mode == 2) {
                v0 = fmaxf(v0, 0.f); v1 = fmaxf(v1, 0.f);
                v2 = fmaxf(v2, 0.f); v3 = fmaxf(v3, 0.f);
                size_t i0 = row0 * (size_t)Nn + col0;
                size_t i2 = (row0 + 8) * (size_t)Nn + col0;
                split_write(Ch, Cl, i0, v0);
                split_write(Ch, Cl, i2, v2);
                if (col0 + 1 < Nn) {
                    split_write(Ch, Cl, i0 + 1, v1);
                    split_write(Ch, Cl, i2 + 1, v3);
                }
            } else {
                C[row0 * (size_t)Nn + col0]       = v0;
                C[(row0 + 8) * (size_t)Nn + col0] = v2;
                if (col0 + 1 < Nn) {
                    C[row0 * (size_t)Nn + col0 + 1]       = v1;
                    C[(row0 + 8) * (size_t)Nn + col0 + 1] = v3;
                }
            }
        }
}

// ---------------- CSR build (group edges by destination c = ei[e][1]) --------
__global__ void k_zero(int* deg, int* fill) {
    int i = blockIdx.x * blockDim.x + threadIdx.x;
    if (i < NN) { deg[i] = 0; fill[i] = 0; }
}
__global__ void k_count(const int* __restrict__ ei, int* deg) {
    int e = blockIdx.x * blockDim.x + threadIdx.x;
    if (e < EE) atomicAdd(&deg[ei[2 * e + 1]], 1);
}
__global__ void k_scan(const int* __restrict__ deg, int* __restrict__ off) {
    __shared__ int s[NN];
    for (int i = threadIdx.x; i < NN; i += blockDim.x) s[i] = deg[i];
    __syncthreads();
    if (threadIdx.x == 0) {
        int acc = 0;
        for (int i = 0; i < NN; i++) { int d = s[i]; s[i] = acc; acc += d; }
    }
    __syncthreads();
    for (int i = threadIdx.x; i < NN; i += blockDim.x) off[i] = s[i];
    if (threadIdx.x == 0) off[NN] = EE;
}
__global__ void k_fill(const int* __restrict__ ei, const int* __restrict__ off,
                       int* fill, int* eidx) {
    int e = blockIdx.x * blockDim.x + threadIdx.x;
    if (e < EE) {
        int c = ei[2 * e + 1];
        int p = atomicAdd(&fill[c], 1);
        eidx[off[c] + p] = e;
    }
}

// ---------------- attention scores: per edge, per head dot(q[c], k[r]) -------
__global__ __launch_bounds__(256) void scores_kernel(
    const float* __restrict__ q, const float* __restrict__ k,
    const int* __restrict__ ei, float* __restrict__ scores)
{
    int e = blockIdx.x;
    int r = ei[2 * e], c = ei[2 * e + 1];
    int t = threadIdx.x;
    int h = t >> 5, lane = t & 31;
    const float* qp = q + (size_t)c * DD + h * DHH;
    const float* kp = k + (size_t)r * DD + h * DHH;
    float s = 0.f;
#pragma unroll
    for (int j = 0; j < 8; j++) {
        int d = lane + 32 * j;
        s = fmaf(qp[d], kp[d], s);
    }
#pragma unroll
    for (int o = 16; o; o >>= 1) s += __shfl_xor_sync(0xffffffffu, s, o);
    if (lane == 0) scores[(size_t)e * HH + h] = s * SCALE;
}

// ---------------- softmax + weighted aggregation per (node, head) ------------
// writes bf16 hi/lo split of agg directly (consumed by the Wo GEMM)
__global__ __launch_bounds__(256) void attn_agg_kernel(
    const float* __restrict__ scores, const float* __restrict__ v,
    const int* __restrict__ ei, const int* __restrict__ off,
    const int* __restrict__ eidx,
    __nv_bfloat16* __restrict__ aggh, __nv_bfloat16* __restrict__ aggl)
{
    int n = blockIdx.x, h = blockIdx.y;
    int t = threadIdx.x;   // 256 == DHH
    int beg = off[n], end = off[n + 1];
    __shared__ float sh[256];

    float mx = -3.4e38f;
    for (int i = beg + t; i < end; i += 256)
        mx = fmaxf(mx, scores[(size_t)eidx[i] * HH + h]);
    sh[t] = mx; __syncthreads();
    for (int s2 = 128; s2; s2 >>= 1) {
        if (t < s2) sh[t] = fmaxf(sh[t], sh[t + s2]);
        __syncthreads();
    }
    float m = sh[0]; __syncthreads();

    float se = 0.f;
    for (int i = beg + t; i < end; i += 256)
        se += __expf(scores[(size_t)eidx[i] * HH + h] - m);
    sh[t] = se; __syncthreads();
    for (int s2 = 128; s2; s2 >>= 1) {
        if (t < s2) sh[t] += sh[t + s2];
        __syncthreads();
    }
    float den = sh[0];

    float acc = 0.f;
    for (int i = beg; i < end; i++) {
        int e = eidx[i];
        int src = ei[2 * e];
        float w = __expf(scores[(size_t)e * HH + h] - m);
        acc = fmaf(w, v[(size_t)src * DD + h * DHH + t], acc);
    }
    float val = (end > beg) ? (acc / den) : 0.f;
    split_write(aggh, aggl, (size_t)n * DD + h * DHH + t, val);
}

// ---------------- residual add + LayerNorm (in place on x; also split out) ----
__global__ __launch_bounds__(256) void add_ln_kernel(
    float* __restrict__ x, const float* __restrict__ x2,
    const float* __restrict__ g, const float* __restrict__ b,
    __nv_bfloat16* __restrict__ xh, __nv_bfloat16* __restrict__ xl)
{
    int n = blockIdx.x, t = threadIdx.x;
    size_t base = (size_t)n * DD;
    float loc[8];
    float s = 0.f, ss = 0.f;
#pragma unroll
    for (int j = 0; j < 8; j++) {
        int d = t + 256 * j;
        float vv = x[base + d] + x2[base + d];
        loc[j] = vv; s += vv; ss = fmaf(vv, vv, ss);
    }
    __shared__ float sh1[8], sh2[8];
#pragma unroll
    for (int o = 16; o; o >>= 1) {
        s  += __shfl_xor_sync(0xffffffffu, s, o);
        ss += __shfl_xor_sync(0xffffffffu, ss, o);
    }
    int w = t >> 5, lane = t & 31;
    if (lane == 0) { sh1[w] = s; sh2[w] = ss; }
    __syncthreads();
    if (t == 0) {
        float a = 0.f, c2 = 0.f;
        for (int i = 0; i < 8; i++) { a += sh1[i]; c2 += sh2[i]; }
        sh1[0] = a; sh2[0] = c2;
    }
    __syncthreads();
    float mean = sh1[0] * (1.0f / DD);
    float var  = sh2[0] * (1.0f / DD) - mean * mean;
    float inv  = rsqrtf(var + 1e-5f);
#pragma unroll
    for (int j = 0; j < 8; j++) {
        int d = t + 256 * j;
        float o2 = (loc[j] - mean) * inv * g[d] + b[d];
        x[base + d] = o2;
        split_write(xh, xl, base + d, o2);
    }
}

// ---------------- host launcher ----------------------------------------------
extern "C" void kernel_launch(void* const* d_in, const int* in_sizes, int n_in,
                              void* d_out, int out_size)
{
    const float* feats = (const float*)d_in[0];
    const int*   ei    = (const int*)  d_in[1];
    const float* Wq  = (const float*)d_in[2];
    const float* bq  = (const float*)d_in[3];
    const float* Wk  = (const float*)d_in[4];
    const float* bk  = (const float*)d_in[5];
    const float* Wv  = (const float*)d_in[6];
    const float* bv  = (const float*)d_in[7];
    const float* Wo  = (const float*)d_in[8];
    const float* bo  = (const float*)d_in[9];
    const float* W1  = (const float*)d_in[10];
    const float* b1  = (const float*)d_in[11];
    const float* W2  = (const float*)d_in[12];
    const float* b2  = (const float*)d_in[13];
    const float* g1  = (const float*)d_in[14];
    const float* be1 = (const float*)d_in[15];
    const float* g2  = (const float*)d_in[16];
    const float* be2 = (const float*)d_in[17];
    const float* Wfc = (const float*)d_in[18];
    const float* bfc = (const float*)d_in[19];
    float* out = (float*)d_out;

    float *x, *q, *k, *v, *tmp, *scores;
    int *deg, *off, *fill, *eidx;
    __nv_bfloat16 *xh, *xl, *hh, *hl;
    __nv_bfloat16 *wqh, *wql, *wkh, *wkl, *wvh, *wvl, *woh, *wol;
    __nv_bfloat16 *w1h, *w1l, *w2h, *w2l, *wfh, *wfl;

    cudaGetSymbolAddress((void**)&x,      g_x);
    cudaGetSymbolAddress((void**)&q,      g_q);
    cudaGetSymbolAddress((void**)&k,      g_k);
    cudaGetSymbolAddress((void**)&v,      g_v);
    cudaGetSymbolAddress((void**)&tmp,    g_tmp);
    cudaGetSymbolAddress((void**)&scores, g_scores);
    cudaGetSymbolAddress((void**)&deg,    g_deg);
    cudaGetSymbolAddress((void**)&off,    g_off);
    cudaGetSymbolAddress((void**)&fill,   g_fill);
    cudaGetSymbolAddress((void**)&eidx,   g_eidx);
    cudaGetSymbolAddress((void**)&xh,     g_xh);
    cudaGetSymbolAddress((void**)&xl,     g_xl);
    cudaGetSymbolAddress((void**)&hh,     g_hh);
    cudaGetSymbolAddress((void**)&hl,     g_hl);
    cudaGetSymbolAddress((void**)&wqh,    g_wqt_h);
    cudaGetSymbolAddress((void**)&wql,    g_wqt_l);
    cudaGetSymbolAddress((void**)&wkh,    g_wkt_h);
    cudaGetSymbolAddress((void**)&wkl,    g_wkt_l);
    cudaGetSymbolAddress((void**)&wvh,    g_wvt_h);
    cudaGetSymbolAddress((void**)&wvl,    g_wvt_l);
    cudaGetSymbolAddress((void**)&woh,    g_wot_h);
    cudaGetSymbolAddress((void**)&wol,    g_wot_l);
    cudaGetSymbolAddress((void**)&w1h,    g_w1t_h);
    cudaGetSymbolAddress((void**)&w1l,    g_w1t_l);
    cudaGetSymbolAddress((void**)&w2h,    g_w2t_h);
    cudaGetSymbolAddress((void**)&w2l,    g_w2t_l);
    cudaGetSymbolAddress((void**)&wfh,    g_wfct_h);
    cudaGetSymbolAddress((void**)&wfl,    g_wfct_l);

    cudaFuncSetAttribute(bf16x3_gemm,
                         cudaFuncAttributeMaxDynamicSharedMemorySize, GEMM_SMEM);

    cudaMemcpyAsync(x, feats, (size_t)NN * DD * sizeof(float),
                    cudaMemcpyDeviceToDevice, 0);

    // CSR build
    k_zero <<<(NN + 255) / 256, 256>>>(deg, fill);
    k_count<<<(EE + 255) / 256, 256>>>(ei, deg);
    k_scan <<<1, 1024>>>(deg, off);
    k_fill <<<(EE + 255) / 256, 256>>>(ei, off, fill, eidx);

    // Weight conversion (transpose + bf16 hi/lo split)
    dim3 tsb(32, 8);
    for (int i = 0; i < LL; i++) {
        size_t oD = (size_t)i * DD * DD, oH = (size_t)i * DD * HIDD;
        transpose_split_kernel<<<dim3(64, 64),  tsb>>>(Wq + oD, wqh + oD, wql + oD, DD, DD, DD);
        transpose_split_kernel<<<dim3(64, 64),  tsb>>>(Wk + oD, wkh + oD, wkl + oD, DD, DD, DD);
        transpose_split_kernel<<<dim3(64, 64),  tsb>>>(Wv + oD, wvh + oD, wvl + oD, DD, DD, DD);
        transpose_split_kernel<<<dim3(64, 64),  tsb>>>(Wo + oD, woh + oD, wol + oD, DD, DD, DD);
        transpose_split_kernel<<<dim3(64, 256), tsb>>>(W1 + oH, w1h + oH, w1l + oH, DD, HIDD, HIDD);
        transpose_split_kernel<<<dim3(256, 64), tsb>>>(W2 + oH, w2h + oH, w2l + oH, HIDD, DD, DD);
    }
    transpose_split_kernel<<<dim3(64, 24), tsb>>>(Wfc, wfh, wfl, DD, NC, NCPAD);

    const size_t nXD = (size_t)NN * DD;
    split_kernel<<<(unsigned)((nXD + 255) / 256), 256>>>(x, xh, xl, nXD);

    dim3 gD(DD / BNg,    NN / BMg);   // (16, 16)
    dim3 gH(HIDD / BNg,  NN / BMg);   // (64, 16)
    dim3 gF(NCPAD / BNg, NN / BMg);   // (6, 16)

    for (int i = 0; i < LL; i++) {
        size_t oD = (size_t)i * DD * DD, oH = (size_t)i * DD * HIDD;

        bf16x3_gemm<<<gD, GEMM_THREADS, GEMM_SMEM>>>(
            xh, xl, wqh + oD, wql + oD, bq + (size_t)i * DD, q, nullptr, nullptr, DD, DD, 0);
        bf16x3_gemm<<<gD, GEMM_THREADS, GEMM_SMEM>>>(
            xh, xl, wkh + oD, wkl + oD, bk + (size_t)i * DD, k, nullptr, nullptr, DD, DD, 0);
        bf16x3_gemm<<<gD, GEMM_THREADS, GEMM_SMEM>>>(
            xh, xl, wvh + oD, wvl + oD, bv + (size_t)i * DD, v, nullptr, nullptr, DD, DD, 0);

        scores_kernel<<<EE, 256>>>(q, k, ei, scores);
        attn_agg_kernel<<<dim3(NN, HH), 256>>>(scores, v, ei, off, eidx, xh, xl);

        bf16x3_gemm<<<gD, GEMM_THREADS, GEMM_SMEM>>>(
            xh, xl, woh + oD, wol + oD, bo + (size_t)i * DD, tmp, nullptr, nullptr, DD, DD, 0);
        add_ln_kernel<<<NN, 256>>>(x, tmp, g1 + (size_t)i * DD, be1 + (size_t)i * DD, xh, xl);

        bf16x3_gemm<<<gH, GEMM_THREADS, GEMM_SMEM>>>(
            xh, xl, w1h + oH, w1l + oH, b1 + (size_t)i * HIDD, nullptr, hh, hl, DD, HIDD, 2);
        bf16x3_gemm<<<gD, GEMM_THREADS, GEMM_SMEM>>>(
            hh, hl, w2h + oH, w2l + oH, b2 + (size_t)i * DD, tmp, nullptr, nullptr, HIDD, DD, 0);
        add_ln_kernel<<<NN, 256>>>(x, tmp, g2 + (size_t)i * DD, be2 + (size_t)i * DD, xh, xl);
    }

    // logits -> first N*NC floats; then x -> remaining N*D floats
    bf16x3_gemm<<<gF, GEMM_THREADS, GEMM_SMEM>>>(
        xh, xl, wfh, wfl, bfc, out, nullptr, nullptr, DD, NC, 0);
    cudaMemcpyAsync(out + (size_t)NN * NC, x, (size_t)NN * DD * sizeof(float),
                    cudaMemcpyDeviceToDevice, 0);
}

// round 11
// speedup vs baseline: 4.3145x; 1.4190x over previous
#include <cuda_runtime.h>
#include <cuda_fp16.h>
#include <cstdint>
#include <math.h>

// Problem constants
#define NN    4096
#define DD    2048
#define HH    8
#define DHH   256
#define HIDD  8192
#define EE    65536
#define LL    2
#define NC    751
#define NCPAD 768
#define SCALE 0.0625f   // 1/sqrt(256)

// GEMM tiling (mma.sync path — works under plain sm_103 PTX target)
#define BMg 256
#define BNg 128
#define BKg 32
#define STAGES 4
#define STAGE_BYTES 40960          // Ah 16K | Al 16K | B 8K
#define GEMM_SMEM (STAGES * STAGE_BYTES)
#define GEMM_THREADS 512

// ---------------- scratch (device globals; no allocation allowed) -------------
__device__ __align__(16) float g_x  [(size_t)NN * DD];
__device__ __align__(16) float g_q  [(size_t)NN * DD];
__device__ __align__(16) float g_k  [(size_t)NN * DD];
__device__ __align__(16) float g_v  [(size_t)NN * DD];
__device__ __align__(16) float g_tmp[(size_t)NN * DD];
__device__ __align__(16) float g_scores[(size_t)EE * HH];
__device__ int   g_deg [NN];
__device__ int   g_off [NN + 1];
__device__ int   g_fill[NN];
__device__ int   g_eidx[EE];

// fp16 hi/lo splits of activations (A operand)
__device__ __align__(16) __half g_xh[(size_t)NN * DD];
__device__ __align__(16) __half g_xl[(size_t)NN * DD];
__device__ __align__(16) __half g_hh[(size_t)NN * HIDD];
__device__ __align__(16) __half g_hl[(size_t)NN * HIDD];

// Transposed fp16 weights ([N][K] layout per layer) — single copy (B operand)
__device__ __align__(16) __half g_wqt[(size_t)LL * DD * DD];
__device__ __align__(16) __half g_wkt[(size_t)LL * DD * DD];
__device__ __align__(16) __half g_wvt[(size_t)LL * DD * DD];
__device__ __align__(16) __half g_wot[(size_t)LL * DD * DD];
__device__ __align__(16) __half g_w1t[(size_t)LL * HIDD * DD];
__device__ __align__(16) __half g_w2t[(size_t)LL * DD * HIDD];
__device__ __align__(16) __half g_wfct[(size_t)NCPAD * DD];

// ---------------- PTX helpers (sm_80-level only) ------------------------------
__device__ __forceinline__ uint32_t smem_u32(const void* p) {
    uint32_t a;
    asm("{ .reg .u64 t; cvta.to.shared.u64 t, %1; cvt.u32.u64 %0, t; }"
        : "=r"(a) : "l"(p));
    return a;
}
__device__ __forceinline__ void cp16(uint32_t s, const void* g) {
    asm volatile("cp.async.cg.shared.global [%0], [%1], 16;" :: "r"(s), "l"(g));
}
__device__ __forceinline__ void cp_commit() {
    asm volatile("cp.async.commit_group;" ::: "memory");
}
__device__ __forceinline__ void cp_wait2() {
    asm volatile("cp.async.wait_group 2;" ::: "memory");
}
__device__ __forceinline__ void ldsm4(uint32_t* r, uint32_t a) {
    asm volatile("ldmatrix.sync.aligned.m8n8.x4.shared.b16 {%0,%1,%2,%3}, [%4];"
                 : "=r"(r[0]), "=r"(r[1]), "=r"(r[2]), "=r"(r[3]) : "r"(a));
}
__device__ __forceinline__ void mma16816(float* d, const uint32_t* a, const uint32_t* b) {
    asm volatile("mma.sync.aligned.m16n8k16.row.col.f32.f16.f16.f32 "
                 "{%0,%1,%2,%3}, {%4,%5,%6,%7}, {%8,%9}, {%0,%1,%2,%3};"
                 : "+f"(d[0]), "+f"(d[1]), "+f"(d[2]), "+f"(d[3])
                 : "r"(a[0]), "r"(a[1]), "r"(a[2]), "r"(a[3]),
                   "r"(b[0]), "r"(b[1]));
}
// 64B rows, 4x16B chunks, XOR swizzle keeps ldmatrix reads conflict-free
__device__ __forceinline__ uint32_t tile_addr(uint32_t base, int row, int chunk) {
    return base + (uint32_t)(row * 64) + (uint32_t)((chunk ^ ((row >> 1) & 3)) * 16);
}
__device__ __forceinline__ void split_write(__half* hi, __half* lo,
                                            size_t idx, float v) {
    __half h = __float2half_rn(v);
    hi[idx] = h;
    lo[idx] = __float2half_rn(v - __half2float(h));
}

// ---------------- conversion kernels -----------------------------------------
__global__ void split_kernel(const float* __restrict__ X,
                             __half* __restrict__ hi,
                             __half* __restrict__ lo, size_t n) {
    size_t i = (size_t)blockIdx.x * blockDim.x + threadIdx.x;
    if (i < n) split_write(hi, lo, i, X[i]);
}

// W [K, Nn] fp32 row-major -> out [Npad, K] fp16 (rows >= Nn zero-filled)
__global__ void transpose_f16_kernel(const float* __restrict__ W,
                                     __half* __restrict__ Wt,
                                     int K, int Nn, int Npad) {
    __shared__ float tile[32][33];
    int k0 = blockIdx.x * 32, n0 = blockIdx.y * 32;
    int tx = threadIdx.x, ty = threadIdx.y;   // 32 x 8
#pragma unroll
    for (int j = 0; j < 32; j += 8) {
        int k = k0 + ty + j, n = n0 + tx;
        tile[ty + j][tx] = (k < K && n < Nn) ? W[(size_t)k * Nn + n] : 0.f;
    }
    __syncthreads();
#pragma unroll
    for (int j = 0; j < 32; j += 8) {
        int n = n0 + ty + j, k = k0 + tx;
        if (n < Npad && k < K)
            Wt[(size_t)n * K + k] = __float2half_rn(tile[tx][ty + j]);
    }
}

// ---------------- fp16x2 GEMM on mma.sync (HMMA) ------------------------------
// C = (Ah+Al)[M,K] @ B^T[Npad,K] + bias
// mode 0: fp32 C; mode 2: relu + fp16 hi/lo split outputs (Ch/Cl)
// grid = (Npad/128, M/256), 512 threads. 4-stage cp.async pipeline.
__global__ __launch_bounds__(GEMM_THREADS, 1) void f16x2_gemm(
    const __half* __restrict__ Ah, const __half* __restrict__ Al,
    const __half* __restrict__ B,
    const float* __restrict__ bias, float* __restrict__ C,
    __half* __restrict__ Ch, __half* __restrict__ Cl,
    int K, int Nn, int mode)
{
    extern __shared__ char smem[];
    const uint32_t sb = smem_u32(smem);
    const int tid  = threadIdx.x;
    const int wid  = tid >> 5, lane = tid & 31;
    const int warpM = wid & 7;          // 8 warps along M (8*32 = 256)
    const int warpN = wid >> 3;         // 2 warps along N (2*64 = 128)
    const int g  = lane >> 3;           // ldmatrix address group
    const int lr = lane & 7;
    const size_t rowBase = (size_t)blockIdx.y * BMg;
    const size_t nBase   = (size_t)blockIdx.x * BNg;
    const int colBase    = blockIdx.x * BNg;
    const int nT = K / BKg;

    float acc[16][4];
#pragma unroll
    for (int i = 0; i < 16; i++)
#pragma unroll
        for (int j = 0; j < 4; j++) acc[i][j] = 0.f;

    // per-stage: 2560 16B chunks (Ah 1024 | Al 1024 | B 512), 5/thread
    auto load_stage = [&](int stage, int kt) {
        const uint32_t st = sb + stage * STAGE_BYTES;
        const int k0 = kt * BKg;
#pragma unroll
        for (int i = 0; i < 5; i++) {
            int c = tid + i * GEMM_THREADS;
            uint32_t soff;
            const __half* gp;
            if (c < 2048) {
                int reg = c >> 10;
                int idx = c & 1023;
                int row = idx >> 2, ch = idx & 3;
                soff = (uint32_t)reg * 16384u + (uint32_t)(row * 64)
                     + (uint32_t)((ch ^ ((row >> 1) & 3)) * 16);
                gp = (reg ? Al : Ah) + (rowBase + row) * (size_t)K + k0 + ch * 8;
            } else {
                int idx = c - 2048;
                int row = idx >> 2, ch = idx & 3;
                soff = 32768u + (uint32_t)(row * 64)
                     + (uint32_t)((ch ^ ((row >> 1) & 3)) * 16);
                gp = B + (nBase + row) * (size_t)K + k0 + ch * 8;
            }
            cp16(st + soff, gp);
        }
    };

    // prologue: stages 0..2
    load_stage(0, 0); cp_commit();
    load_stage(1, 1); cp_commit();
    load_stage(2, 2); cp_commit();

    const int mOff = warpM * 32;
    const int nOff = warpN * 64;

    for (int kt = 0; kt < nT; kt++) {
        cp_wait2();            // stage kt data arrived (<=2 groups pending)
        __syncthreads();       // all warps done with stage (kt-1)%4 reads
        if (kt + 3 < nT) load_stage((kt + 3) & 3, kt + 3);
        cp_commit();           // always commit to keep group numbering

        const uint32_t st = sb + (kt & 3) * STAGE_BYTES;
        const uint32_t aB  = st;
        const uint32_t alB = st + 16384;
        const uint32_t bB  = st + 32768;

#pragma unroll
        for (int ks = 0; ks < 2; ks++) {
            uint32_t ahf[2][4], alf[2][4];
#pragma unroll
            for (int mt = 0; mt < 2; mt++) {
                int r = mOff + mt * 16 + lr + (g & 1) * 8;
                int ch = 2 * ks + (g >> 1);
                ldsm4(ahf[mt], tile_addr(aB,  r, ch));
                ldsm4(alf[mt], tile_addr(alB, r, ch));
            }
#pragma unroll
            for (int p = 0; p < 4; p++) {
                uint32_t bf[4];
                int r = nOff + p * 16 + lr + (g >> 1) * 8;
                int ch = 2 * ks + (g & 1);
                ldsm4(bf, tile_addr(bB, r, ch));
#pragma unroll
                for (int mt = 0; mt < 2; mt++) {
                    float* d0 = acc[mt * 8 + 2 * p];
                    float* d1 = acc[mt * 8 + 2 * p + 1];
                    mma16816(d0, ahf[mt], bf);
                    mma16816(d0, alf[mt], bf);
                    mma16816(d1, ahf[mt], bf + 2);
                    mma16816(d1, alf[mt], bf + 2);
                }
            }
        }
    }

    // epilogue (fragment: rows lane>>2, +8; cols 2*(lane&3), +1)
#pragma unroll
    for (int mt = 0; mt < 2; mt++)
#pragma unroll
        for (int nt = 0; nt < 8; nt++) {
            const float* d = acc[mt * 8 + nt];
            size_t row0 = rowBase + mOff + mt * 16 + (lane >> 2);
            int col0 = colBase + nOff + nt * 8 + (lane & 3) * 2;
            if (col0 >= Nn) continue;
            float b0 = bias[col0];
            float b1 = (col0 + 1 < Nn) ? bias[col0 + 1] : 0.f;
            float v0 = d[0] + b0, v1 = d[1] + b1;
            float v2 = d[2] + b0, v3 = d[3] + b1;
            if (mode == 2) {
                v0 = fmaxf(v0, 0.f); v1 = fmaxf(v1, 0.f);
                v2 = fmaxf(v2, 0.f); v3 = fmaxf(v3, 0.f);
                size_t i0 = row0 * (size_t)Nn + col0;
                size_t i2 = (row0 + 8) * (size_t)Nn + col0;
                split_write(Ch, Cl, i0, v0);
                split_write(Ch, Cl, i2, v2);
                if (col0 + 1 < Nn) {
                    split_write(Ch, Cl, i0 + 1, v1);
                    split_write(Ch, Cl, i2 + 1, v3);
                }
            } else {
                C[row0 * (size_t)Nn + col0]       = v0;
                C[(row0 + 8) * (size_t)Nn + col0] = v2;
                if (col0 + 1 < Nn) {
                    C[row0 * (size_t)Nn + col0 + 1]       = v1;
                    C[(row0 + 8) * (size_t)Nn + col0 + 1] = v3;
                }
            }
        }
}

// ---------------- CSR build (group edges by destination c = ei[e][1]) --------
__global__ void k_zero(int* deg, int* fill) {
    int i = blockIdx.x * blockDim.x + threadIdx.x;
    if (i < NN) { deg[i] = 0; fill[i] = 0; }
}
__global__ void k_count(const int* __restrict__ ei, int* deg) {
    int e = blockIdx.x * blockDim.x + threadIdx.x;
    if (e < EE) atomicAdd(&deg[ei[2 * e + 1]], 1);
}
__global__ void k_scan(const int* __restrict__ deg, int* __restrict__ off) {
    __shared__ int s[NN];
    for (int i = threadIdx.x; i < NN; i += blockDim.x) s[i] = deg[i];
    __syncthreads();
    if (threadIdx.x == 0) {
        int acc = 0;
        for (int i = 0; i < NN; i++) { int d = s[i]; s[i] = acc; acc += d; }
    }
    __syncthreads();
    for (int i = threadIdx.x; i < NN; i += blockDim.x) off[i] = s[i];
    if (threadIdx.x == 0) off[NN] = EE;
}
__global__ void k_fill(const int* __restrict__ ei, const int* __restrict__ off,
                       int* fill, int* eidx) {
    int e = blockIdx.x * blockDim.x + threadIdx.x;
    if (e < EE) {
        int c = ei[2 * e + 1];
        int p = atomicAdd(&fill[c], 1);
        eidx[off[c] + p] = e;
    }
}

// ---------------- attention scores: per edge, per head dot(q[c], k[r]) -------
__global__ __launch_bounds__(256) void scores_kernel(
    const float* __restrict__ q, const float* __restrict__ k,
    const int* __restrict__ ei, float* __restrict__ scores)
{
    int e = blockIdx.x;
    int r = ei[2 * e], c = ei[2 * e + 1];
    int t = threadIdx.x;
    int h = t >> 5, lane = t & 31;
    const float* qp = q + (size_t)c * DD + h * DHH;
    const float* kp = k + (size_t)r * DD + h * DHH;
    float s = 0.f;
#pragma unroll
    for (int j = 0; j < 8; j++) {
        int d = lane + 32 * j;
        s = fmaf(qp[d], kp[d], s);
    }
#pragma unroll
    for (int o = 16; o; o >>= 1) s += __shfl_xor_sync(0xffffffffu, s, o);
    if (lane == 0) scores[(size_t)e * HH + h] = s * SCALE;
}

// ---------------- softmax + weighted aggregation per (node, head) ------------
// writes fp16 hi/lo split of agg directly (consumed by the Wo GEMM)
__global__ __launch_bounds__(256) void attn_agg_kernel(
    const float* __restrict__ scores, const float* __restrict__ v,
    const int* __restrict__ ei, const int* __restrict__ off,
    const int* __restrict__ eidx,
    __half* __restrict__ aggh, __half* __restrict__ aggl)
{
    int n = blockIdx.x, h = blockIdx.y;
    int t = threadIdx.x;   // 256 == DHH
    int beg = off[n], end = off[n + 1];
    __shared__ float sh[256];

    float mx = -3.4e38f;
    for (int i = beg + t; i < end; i += 256)
        mx = fmaxf(mx, scores[(size_t)eidx[i] * HH + h]);
    sh[t] = mx; __syncthreads();
    for (int s2 = 128; s2; s2 >>= 1) {
        if (t < s2) sh[t] = fmaxf(sh[t], sh[t + s2]);
        __syncthreads();
    }
    float m = sh[0]; __syncthreads();

    float se = 0.f;
    for (int i = beg + t; i < end; i += 256)
        se += __expf(scores[(size_t)eidx[i] * HH + h] - m);
    sh[t] = se; __syncthreads();
    for (int s2 = 128; s2; s2 >>= 1) {
        if (t < s2) sh[t] += sh[t + s2];
        __syncthreads();
    }
    float den = sh[0];

    float acc = 0.f;
    for (int i = beg; i < end; i++) {
        int e = eidx[i];
        int src = ei[2 * e];
        float w = __expf(scores[(size_t)e * HH + h] - m);
        acc = fmaf(w, v[(size_t)src * DD + h * DHH + t], acc);
    }
    float val = (end > beg) ? (acc / den) : 0.f;
    split_write(aggh, aggl, (size_t)n * DD + h * DHH + t, val);
}

// ---------------- residual add + LayerNorm (in place on x; also split out) ----
__global__ __launch_bounds__(256) void add_ln_kernel(
    float* __restrict__ x, const float* __restrict__ x2,
    const float* __restrict__ g, const float* __restrict__ b,
    __half* __restrict__ xh, __half* __restrict__ xl)
{
    int n = blockIdx.x, t = threadIdx.x;
    size_t base = (size_t)n * DD;
    float loc[8];
    float s = 0.f, ss = 0.f;
#pragma unroll
    for (int j = 0; j < 8; j++) {
        int d = t + 256 * j;
        float vv = x[base + d] + x2[base + d];
        loc[j] = vv; s += vv; ss = fmaf(vv, vv, ss);
    }
    __shared__ float sh1[8], sh2[8];
#pragma unroll
    for (int o = 16; o; o >>= 1) {
        s  += __shfl_xor_sync(0xffffffffu, s, o);
        ss += __shfl_xor_sync(0xffffffffu, ss, o);
    }
    int w = t >> 5, lane = t & 31;
    if (lane == 0) { sh1[w] = s; sh2[w] = ss; }
    __syncthreads();
    if (t == 0) {
        float a = 0.f, c2 = 0.f;
        for (int i = 0; i < 8; i++) { a += sh1[i]; c2 += sh2[i]; }
        sh1[0] = a; sh2[0] = c2;
    }
    __syncthreads();
    float mean = sh1[0] * (1.0f / DD);
    float var  = sh2[0] * (1.0f / DD) - mean * mean;
    float inv  = rsqrtf(var + 1e-5f);
#pragma unroll
    for (int j = 0; j < 8; j++) {
        int d = t + 256 * j;
        float o2 = (loc[j] - mean) * inv * g[d] + b[d];
        x[base + d] = o2;
        split_write(xh, xl, base + d, o2);
    }
}

// ---------------- host launcher ----------------------------------------------
extern "C" void kernel_launch(void* const* d_in, const int* in_sizes, int n_in,
                              void* d_out, int out_size)
{
    const float* feats = (const float*)d_in[0];
    const int*   ei    = (const int*)  d_in[1];
    const float* Wq  = (const float*)d_in[2];
    const float* bq  = (const float*)d_in[3];
    const float* Wk  = (const float*)d_in[4];
    const float* bk  = (const float*)d_in[5];
    const float* Wv  = (const float*)d_in[6];
    const float* bv  = (const float*)d_in[7];
    const float* Wo  = (const float*)d_in[8];
    const float* bo  = (const float*)d_in[9];
    const float* W1  = (const float*)d_in[10];
    const float* b1  = (const float*)d_in[11];
    const float* W2  = (const float*)d_in[12];
    const float* b2  = (const float*)d_in[13];
    const float* g1  = (const float*)d_in[14];
    const float* be1 = (const float*)d_in[15];
    const float* g2  = (const float*)d_in[16];
    const float* be2 = (const float*)d_in[17];
    const float* Wfc = (const float*)d_in[18];
    const float* bfc = (const float*)d_in[19];
    float* out = (float*)d_out;

    float *x, *q, *k, *v, *tmp, *scores;
    int *deg, *off, *fill, *eidx;
    __half *xh, *xl, *hh, *hl;
    __half *wq_, *wk_, *wv_, *wo_, *w1_, *w2_, *wf_;

    cudaGetSymbolAddress((void**)&x,      g_x);
    cudaGetSymbolAddress((void**)&q,      g_q);
    cudaGetSymbolAddress((void**)&k,      g_k);
    cudaGetSymbolAddress((void**)&v,      g_v);
    cudaGetSymbolAddress((void**)&tmp,    g_tmp);
    cudaGetSymbolAddress((void**)&scores, g_scores);
    cudaGetSymbolAddress((void**)&deg,    g_deg);
    cudaGetSymbolAddress((void**)&off,    g_off);
    cudaGetSymbolAddress((void**)&fill,   g_fill);
    cudaGetSymbolAddress((void**)&eidx,   g_eidx);
    cudaGetSymbolAddress((void**)&xh,     g_xh);
    cudaGetSymbolAddress((void**)&xl,     g_xl);
    cudaGetSymbolAddress((void**)&hh,     g_hh);
    cudaGetSymbolAddress((void**)&hl,     g_hl);
    cudaGetSymbolAddress((void**)&wq_,    g_wqt);
    cudaGetSymbolAddress((void**)&wk_,    g_wkt);
    cudaGetSymbolAddress((void**)&wv_,    g_wvt);
    cudaGetSymbolAddress((void**)&wo_,    g_wot);
    cudaGetSymbolAddress((void**)&w1_,    g_w1t);
    cudaGetSymbolAddress((void**)&w2_,    g_w2t);
    cudaGetSymbolAddress((void**)&wf_,    g_wfct);

    cudaFuncSetAttribute(f16x2_gemm,
                         cudaFuncAttributeMaxDynamicSharedMemorySize, GEMM_SMEM);

    cudaMemcpyAsync(x, feats, (size_t)NN * DD * sizeof(float),
                    cudaMemcpyDeviceToDevice, 0);

    // CSR build
    k_zero <<<(NN + 255) / 256, 256>>>(deg, fill);
    k_count<<<(EE + 255) / 256, 256>>>(ei, deg);
    k_scan <<<1, 1024>>>(deg, off);
    k_fill <<<(EE + 255) / 256, 256>>>(ei, off, fill, eidx);

    // Weight conversion (transpose + fp16)
    dim3 tsb(32, 8);
    for (int i = 0; i < LL; i++) {
        size_t oD = (size_t)i * DD * DD, oH = (size_t)i * DD * HIDD;
        transpose_f16_kernel<<<dim3(64, 64),  tsb>>>(Wq + oD, wq_ + oD, DD, DD, DD);
        transpose_f16_kernel<<<dim3(64, 64),  tsb>>>(Wk + oD, wk_ + oD, DD, DD, DD);
        transpose_f16_kernel<<<dim3(64, 64),  tsb>>>(Wv + oD, wv_ + oD, DD, DD, DD);
        transpose_f16_kernel<<<dim3(64, 64),  tsb>>>(Wo + oD, wo_ + oD, DD, DD, DD);
        transpose_f16_kernel<<<dim3(64, 256), tsb>>>(W1 + oH, w1_ + oH, DD, HIDD, HIDD);
        transpose_f16_kernel<<<dim3(256, 64), tsb>>>(W2 + oH, w2_ + oH, HIDD, DD, DD);
    }
    transpose_f16_kernel<<<dim3(64, 24), tsb>>>(Wfc, wf_, DD, NC, NCPAD);

    const size_t nXD = (size_t)NN * DD;
    split_kernel<<<(unsigned)((nXD + 255) / 256), 256>>>(x, xh, xl, nXD);

    dim3 gD(DD / BNg,    NN / BMg);   // (16, 16)
    dim3 gH(HIDD / BNg,  NN / BMg);   // (64, 16)
    dim3 gF(NCPAD / BNg, NN / BMg);   // (6, 16)

    for (int i = 0; i < LL; i++) {
        size_t oD = (size_t)i * DD * DD, oH = (size_t)i * DD * HIDD;

        f16x2_gemm<<<gD, GEMM_THREADS, GEMM_SMEM>>>(
            xh, xl, wq_ + oD, bq + (size_t)i * DD, q, nullptr, nullptr, DD, DD, 0);
        f16x2_gemm<<<gD, GEMM_THREADS, GEMM_SMEM>>>(
            xh, xl, wk_ + oD, bk + (size_t)i * DD, k, nullptr, nullptr, DD, DD, 0);
        f16x2_gemm<<<gD, GEMM_THREADS, GEMM_SMEM>>>(
            xh, xl, wv_ + oD, bv + (size_t)i * DD, v, nullptr, nullptr, DD, DD, 0);

        scores_kernel<<<EE, 256>>>(q, k, ei, scores);
        attn_agg_kernel<<<dim3(NN, HH), 256>>>(scores, v, ei, off, eidx, xh, xl);

        f16x2_gemm<<<gD, GEMM_THREADS, GEMM_SMEM>>>(
            xh, xl, wo_ + oD, bo + (size_t)i * DD, tmp, nullptr, nullptr, DD, DD, 0);
        add_ln_kernel<<<NN, 256>>>(x, tmp, g1 + (size_t)i * DD, be1 + (size_t)i * DD, xh, xl);

        f16x2_gemm<<<gH, GEMM_THREADS, GEMM_SMEM>>>(
            xh, xl, w1_ + oH, b1 + (size_t)i * HIDD, nullptr, hh, hl, DD, HIDD, 2);
        f16x2_gemm<<<gD, GEMM_THREADS, GEMM_SMEM>>>(
            hh, hl, w2_ + oH, b2 + (size_t)i * DD, tmp, nullptr, nullptr, HIDD, DD, 0);
        add_ln_kernel<<<NN, 256>>>(x, tmp, g2 + (size_t)i * DD, be2 + (size_t)i * DD, xh, xl);
    }

    // logits -> first N*NC floats; then x -> remaining N*D floats
    f16x2_gemm<<<gF, GEMM_THREADS, GEMM_SMEM>>>(
        xh, xl, wf_, bfc, out, nullptr, nullptr, DD, NC, 0);
    cudaMemcpyAsync(out + (size_t)NN * NC, x, (size_t)NN * DD * sizeof(float),
                    cudaMemcpyDeviceToDevice, 0);
}

// round 12
// speedup vs baseline: 6.5534x; 1.5189x over previous
#include <cuda_runtime.h>
#include <cuda_fp16.h>
#include <cstdint>
#include <math.h>

// Problem constants
#define NN    4096
#define DD    2048
#define HH    8
#define DHH   256
#define HIDD  8192
#define EE    65536
#define LL    2
#define NC    751
#define NCPAD 768
#define NQKV  6144
#define SCALE 0.0625f   // 1/sqrt(256)

// GEMM tiling (mma.sync path — works under plain sm_103 PTX target)
#define BMg 256
#define BNg 128
#define BKg 32
#define STAGES 4
#define STAGE_BYTES 24576          // A 16K | B 8K
#define GEMM_SMEM (STAGES * STAGE_BYTES)
#define GEMM_THREADS 512

// ---------------- scratch (device globals; no allocation allowed) -------------
__device__ __align__(16) float g_x  [(size_t)NN * DD];
__device__ __align__(16) float g_qkv[(size_t)NN * NQKV];
__device__ __align__(16) float g_tmp[(size_t)NN * DD];
__device__ __align__(16) float g_scores[(size_t)EE * HH];
__device__ __align__(16) float g_bqkv[(size_t)LL * NQKV];
__device__ int   g_deg [NN];
__device__ int   g_off [NN + 1];
__device__ int   g_fill[NN];
__device__ int   g_eidx[EE];

// fp16 activations (A operand)
__device__ __align__(16) __half g_xh[(size_t)NN * DD];
__device__ __align__(16) __half g_hh[(size_t)NN * HIDD];

// Transposed fp16 weights ([N][K] layout per layer) — B operand
__device__ __align__(16) __half g_wqkvt[(size_t)LL * NQKV * DD];  // Wq|Wk|Wv concat
__device__ __align__(16) __half g_wot[(size_t)LL * DD * DD];
__device__ __align__(16) __half g_w1t[(size_t)LL * HIDD * DD];
__device__ __align__(16) __half g_w2t[(size_t)LL * DD * HIDD];
__device__ __align__(16) __half g_wfct[(size_t)NCPAD * DD];

// ---------------- PTX helpers (sm_80-level only) ------------------------------
__device__ __forceinline__ uint32_t smem_u32(const void* p) {
    uint32_t a;
    asm("{ .reg .u64 t; cvta.to.shared.u64 t, %1; cvt.u32.u64 %0, t; }"
        : "=r"(a) : "l"(p));
    return a;
}
__device__ __forceinline__ void cp16(uint32_t s, const void* g) {
    asm volatile("cp.async.cg.shared.global [%0], [%1], 16;" :: "r"(s), "l"(g));
}
__device__ __forceinline__ void cp_commit() {
    asm volatile("cp.async.commit_group;" ::: "memory");
}
__device__ __forceinline__ void cp_wait2() {
    asm volatile("cp.async.wait_group 2;" ::: "memory");
}
__device__ __forceinline__ void ldsm4(uint32_t* r, uint32_t a) {
    asm volatile("ldmatrix.sync.aligned.m8n8.x4.shared.b16 {%0,%1,%2,%3}, [%4];"
                 : "=r"(r[0]), "=r"(r[1]), "=r"(r[2]), "=r"(r[3]) : "r"(a));
}
__device__ __forceinline__ void mma16816(float* d, const uint32_t* a, const uint32_t* b) {
    asm volatile("mma.sync.aligned.m16n8k16.row.col.f32.f16.f16.f32 "
                 "{%0,%1,%2,%3}, {%4,%5,%6,%7}, {%8,%9}, {%0,%1,%2,%3};"
                 : "+f"(d[0]), "+f"(d[1]), "+f"(d[2]), "+f"(d[3])
                 : "r"(a[0]), "r"(a[1]), "r"(a[2]), "r"(a[3]),
                   "r"(b[0]), "r"(b[1]));
}
// 64B rows, 4x16B chunks, XOR swizzle keeps ldmatrix reads conflict-free
__device__ __forceinline__ uint32_t tile_addr(uint32_t base, int row, int chunk) {
    return base + (uint32_t)(row * 64) + (uint32_t)((chunk ^ ((row >> 1) & 3)) * 16);
}

// ---------------- conversion kernels -----------------------------------------
__global__ void tofp16_kernel(const float* __restrict__ X,
                              __half* __restrict__ o, size_t n) {
    size_t i = (size_t)blockIdx.x * blockDim.x + threadIdx.x;
    if (i < n) o[i] = __float2half_rn(X[i]);
}

// W [K, Nn] fp32 row-major -> out [Npad, K] fp16 (rows >= Nn zero-filled)
__global__ void transpose_f16_kernel(const float* __restrict__ W,
                                     __half* __restrict__ Wt,
                                     int K, int Nn, int Npad) {
    __shared__ float tile[32][33];
    int k0 = blockIdx.x * 32, n0 = blockIdx.y * 32;
    int tx = threadIdx.x, ty = threadIdx.y;   // 32 x 8
#pragma unroll
    for (int j = 0; j < 32; j += 8) {
        int k = k0 + ty + j, n = n0 + tx;
        tile[ty + j][tx] = (k < K && n < Nn) ? W[(size_t)k * Nn + n] : 0.f;
    }
    __syncthreads();
#pragma unroll
    for (int j = 0; j < 32; j += 8) {
        int n = n0 + ty + j, k = k0 + tx;
        if (n < Npad && k < K)
            Wt[(size_t)n * K + k] = __float2half_rn(tile[tx][ty + j]);
    }
}

// pack bq|bk|bv into one contiguous bias vector per layer
__global__ void pack_bias_kernel(const float* __restrict__ bq,
                                 const float* __restrict__ bk,
                                 const float* __restrict__ bv,
                                 float* __restrict__ o) {
    int i = blockIdx.x * blockDim.x + threadIdx.x;   // 0 .. LL*NQKV-1
    int l = i / NQKV, j = i % NQKV;
    float v;
    if (j < DD)            v = bq[l * DD + j];
    else if (j < 2 * DD)   v = bk[l * DD + (j - DD)];
    else                   v = bv[l * DD + (j - 2 * DD)];
    o[i] = v;
}

// ---------------- fp16 GEMM on mma.sync (HMMA) --------------------------------
// C = A[M,K] @ B^T[Npad,K] + bias
// mode 0: fp32 C; mode 2: relu + fp16 output (Ch)
// grid = (Npad/128, M/256), 512 threads. 4-stage cp.async pipeline.
__global__ __launch_bounds__(GEMM_THREADS, 1) void f16_gemm(
    const __half* __restrict__ A, const __half* __restrict__ B,
    const float* __restrict__ bias, float* __restrict__ C,
    __half* __restrict__ Ch,
    int K, int Nn, int mode)
{
    extern __shared__ char smem[];
    const uint32_t sb = smem_u32(smem);
    const int tid  = threadIdx.x;
    const int wid  = tid >> 5, lane = tid & 31;
    const int warpM = wid & 7;          // 8 warps along M (8*32 = 256)
    const int warpN = wid >> 3;         // 2 warps along N (2*64 = 128)
    const int g  = lane >> 3;           // ldmatrix address group
    const int lr = lane & 7;
    const size_t rowBase = (size_t)blockIdx.y * BMg;
    const size_t nBase   = (size_t)blockIdx.x * BNg;
    const int colBase    = blockIdx.x * BNg;
    const int nT = K / BKg;

    float acc[16][4];
#pragma unroll
    for (int i = 0; i < 16; i++)
#pragma unroll
        for (int j = 0; j < 4; j++) acc[i][j] = 0.f;

    // per-stage: 1536 16B chunks (A 1024 | B 512), 3/thread
    auto load_stage = [&](int stage, int kt) {
        const uint32_t st = sb + stage * STAGE_BYTES;
        const int k0 = kt * BKg;
#pragma unroll
        for (int i = 0; i < 3; i++) {
            int c = tid + i * GEMM_THREADS;
            uint32_t soff;
            const __half* gp;
            if (c < 1024) {
                int row = c >> 2, ch = c & 3;
                soff = (uint32_t)(row * 64)
                     + (uint32_t)((ch ^ ((row >> 1) & 3)) * 16);
                gp = A + (rowBase + row) * (size_t)K + k0 + ch * 8;
            } else {
                int idx = c - 1024;
                int row = idx >> 2, ch = idx & 3;
                soff = 16384u + (uint32_t)(row * 64)
                     + (uint32_t)((ch ^ ((row >> 1) & 3)) * 16);
                gp = B + (nBase + row) * (size_t)K + k0 + ch * 8;
            }
            cp16(st + soff, gp);
        }
    };

    // prologue: stages 0..2
    load_stage(0, 0); cp_commit();
    load_stage(1, 1); cp_commit();
    load_stage(2, 2); cp_commit();

    const int mOff = warpM * 32;
    const int nOff = warpN * 64;

    for (int kt = 0; kt < nT; kt++) {
        cp_wait2();            // stage kt data arrived (<=2 groups pending)
        __syncthreads();       // all warps done with stage (kt-1)%4 reads
        if (kt + 3 < nT) load_stage((kt + 3) & 3, kt + 3);
        cp_commit();           // always commit to keep group numbering

        const uint32_t st = sb + (kt & 3) * STAGE_BYTES;
        const uint32_t aB = st;
        const uint32_t bB = st + 16384;

#pragma unroll
        for (int ks = 0; ks < 2; ks++) {
            uint32_t ahf[2][4];
#pragma unroll
            for (int mt = 0; mt < 2; mt++) {
                int r = mOff + mt * 16 + lr + (g & 1) * 8;
                int ch = 2 * ks + (g >> 1);
                ldsm4(ahf[mt], tile_addr(aB, r, ch));
            }
#pragma unroll
            for (int p = 0; p < 4; p++) {
                uint32_t bf[4];
                int r = nOff + p * 16 + lr + (g >> 1) * 8;
                int ch = 2 * ks + (g & 1);
                ldsm4(bf, tile_addr(bB, r, ch));
#pragma unroll
                for (int mt = 0; mt < 2; mt++) {
                    mma16816(acc[mt * 8 + 2 * p],     ahf[mt], bf);
                    mma16816(acc[mt * 8 + 2 * p + 1], ahf[mt], bf + 2);
                }
            }
        }
    }

    // epilogue (fragment: rows lane>>2, +8; cols 2*(lane&3), +1)
#pragma unroll
    for (int mt = 0; mt < 2; mt++)
#pragma unroll
        for (int nt = 0; nt < 8; nt++) {
            const float* d = acc[mt * 8 + nt];
            size_t row0 = rowBase + mOff + mt * 16 + (lane >> 2);
            int col0 = colBase + nOff + nt * 8 + (lane & 3) * 2;
            if (col0 >= Nn) continue;
            float b0 = bias[col0];
            float b1 = (col0 + 1 < Nn) ? bias[col0 + 1] : 0.f;
            float v0 = d[0] + b0, v1 = d[1] + b1;
            float v2 = d[2] + b0, v3 = d[3] + b1;
            if (mode == 2) {
                size_t i0 = row0 * (size_t)Nn + col0;
                size_t i2 = (row0 + 8) * (size_t)Nn + col0;
                Ch[i0] = __float2half_rn(fmaxf(v0, 0.f));
                Ch[i2] = __float2half_rn(fmaxf(v2, 0.f));
                if (col0 + 1 < Nn) {
                    Ch[i0 + 1] = __float2half_rn(fmaxf(v1, 0.f));
                    Ch[i2 + 1] = __float2half_rn(fmaxf(v3, 0.f));
                }
            } else {
                C[row0 * (size_t)Nn + col0]       = v0;
                C[(row0 + 8) * (size_t)Nn + col0] = v2;
                if (col0 + 1 < Nn) {
                    C[row0 * (size_t)Nn + col0 + 1]       = v1;
                    C[(row0 + 8) * (size_t)Nn + col0 + 1] = v3;
                }
            }
        }
}

// ---------------- CSR build (group edges by destination c = ei[e][1]) --------
__global__ void k_zero(int* deg, int* fill) {
    int i = blockIdx.x * blockDim.x + threadIdx.x;
    if (i < NN) { deg[i] = 0; fill[i] = 0; }
}
__global__ void k_count(const int* __restrict__ ei, int* deg) {
    int e = blockIdx.x * blockDim.x + threadIdx.x;
    if (e < EE) atomicAdd(&deg[ei[2 * e + 1]], 1);
}
__global__ void k_scan(const int* __restrict__ deg, int* __restrict__ off) {
    __shared__ int s[NN];
    for (int i = threadIdx.x; i < NN; i += blockDim.x) s[i] = deg[i];
    __syncthreads();
    if (threadIdx.x == 0) {
        int acc = 0;
        for (int i = 0; i < NN; i++) { int d = s[i]; s[i] = acc; acc += d; }
    }
    __syncthreads();
    for (int i = threadIdx.x; i < NN; i += blockDim.x) off[i] = s[i];
    if (threadIdx.x == 0) off[NN] = EE;
}
__global__ void k_fill(const int* __restrict__ ei, const int* __restrict__ off,
                       int* fill, int* eidx) {
    int e = blockIdx.x * blockDim.x + threadIdx.x;
    if (e < EE) {
        int c = ei[2 * e + 1];
        int p = atomicAdd(&fill[c], 1);
        eidx[off[c] + p] = e;
    }
}

// ---------------- attention scores: per edge, per head dot(q[c], k[r]) -------
// qkv layout: [NN][6144], q at +0, k at +2048, v at +4096
__global__ __launch_bounds__(256) void scores_kernel(
    const float* __restrict__ qkv,
    const int* __restrict__ ei, float* __restrict__ scores)
{
    int e = blockIdx.x;
    int r = ei[2 * e], c = ei[2 * e + 1];
    int t = threadIdx.x;
    int h = t >> 5, lane = t & 31;
    const float* qp = qkv + (size_t)c * NQKV + h * DHH;
    const float* kp = qkv + (size_t)r * NQKV + DD + h * DHH;
    float s = 0.f;
#pragma unroll
    for (int j = 0; j < 8; j++) {
        int d = lane + 32 * j;
        s = fmaf(qp[d], kp[d], s);
    }
#pragma unroll
    for (int o = 16; o; o >>= 1) s += __shfl_xor_sync(0xffffffffu, s, o);
    if (lane == 0) scores[(size_t)e * HH + h] = s * SCALE;
}

// ---------------- softmax + weighted aggregation per (node, head) ------------
// writes fp16 agg directly (consumed by the Wo GEMM)
__global__ __launch_bounds__(256) void attn_agg_kernel(
    const float* __restrict__ scores, const float* __restrict__ qkv,
    const int* __restrict__ ei, const int* __restrict__ off,
    const int* __restrict__ eidx,
    __half* __restrict__ aggh)
{
    int n = blockIdx.x, h = blockIdx.y;
    int t = threadIdx.x;   // 256 == DHH
    int beg = off[n], end = off[n + 1];
    __shared__ float sh[256];

    float mx = -3.4e38f;
    for (int i = beg + t; i < end; i += 256)
        mx = fmaxf(mx, scores[(size_t)eidx[i] * HH + h]);
    sh[t] = mx; __syncthreads();
    for (int s2 = 128; s2; s2 >>= 1) {
        if (t < s2) sh[t] = fmaxf(sh[t], sh[t + s2]);
        __syncthreads();
    }
    float m = sh[0]; __syncthreads();

    float se = 0.f;
    for (int i = beg + t; i < end; i += 256)
        se += __expf(scores[(size_t)eidx[i] * HH + h] - m);
    sh[t] = se; __syncthreads();
    for (int s2 = 128; s2; s2 >>= 1) {
        if (t < s2) sh[t] += sh[t + s2];
        __syncthreads();
    }
    float den = sh[0];

    float acc = 0.f;
    for (int i = beg; i < end; i++) {
        int e = eidx[i];
        int src = ei[2 * e];
        float w = __expf(scores[(size_t)e * HH + h] - m);
        acc = fmaf(w, qkv[(size_t)src * NQKV + 2 * DD + h * DHH + t], acc);
    }
    float val = (end > beg) ? (acc / den) : 0.f;
    aggh[(size_t)n * DD + h * DHH + t] = __float2half_rn(val);
}

// ---------------- residual add + LayerNorm (in place on x; also fp16 out) -----
__global__ __launch_bounds__(256) void add_ln_kernel(
    float* __restrict__ x, const float* __restrict__ x2,
    const float* __restrict__ g, const float* __restrict__ b,
    __half* __restrict__ xh)
{
    int n = blockIdx.x, t = threadIdx.x;
    size_t base = (size_t)n * DD;
    float loc[8];
    float s = 0.f, ss = 0.f;
#pragma unroll
    for (int j = 0; j < 8; j++) {
        int d = t + 256 * j;
        float vv = x[base + d] + x2[base + d];
        loc[j] = vv; s += vv; ss = fmaf(vv, vv, ss);
    }
    __shared__ float sh1[8], sh2[8];
#pragma unroll
    for (int o = 16; o; o >>= 1) {
        s  += __shfl_xor_sync(0xffffffffu, s, o);
        ss += __shfl_xor_sync(0xffffffffu, ss, o);
    }
    int w = t >> 5, lane = t & 31;
    if (lane == 0) { sh1[w] = s; sh2[w] = ss; }
    __syncthreads();
    if (t == 0) {
        float a = 0.f, c2 = 0.f;
        for (int i = 0; i < 8; i++) { a += sh1[i]; c2 += sh2[i]; }
        sh1[0] = a; sh2[0] = c2;
    }
    __syncthreads();
    float mean = sh1[0] * (1.0f / DD);
    float var  = sh2[0] * (1.0f / DD) - mean * mean;
    float inv  = rsqrtf(var + 1e-5f);
#pragma unroll
    for (int j = 0; j < 8; j++) {
        int d = t + 256 * j;
        float o2 = (loc[j] - mean) * inv * g[d] + b[d];
        x[base + d] = o2;
        xh[base + d] = __float2half_rn(o2);
    }
}

// ---------------- host launcher ----------------------------------------------
extern "C" void kernel_launch(void* const* d_in, const int* in_sizes, int n_in,
                              void* d_out, int out_size)
{
    const float* feats = (const float*)d_in[0];
    const int*   ei    = (const int*)  d_in[1];
    const float* Wq  = (const float*)d_in[2];
    const float* bq  = (const float*)d_in[3];
    const float* Wk  = (const float*)d_in[4];
    const float* bk  = (const float*)d_in[5];
    const float* Wv  = (const float*)d_in[6];
    const float* bv  = (const float*)d_in[7];
    const float* Wo  = (const float*)d_in[8];
    const float* bo  = (const float*)d_in[9];
    const float* W1  = (const float*)d_in[10];
    const float* b1  = (const float*)d_in[11];
    const float* W2  = (const float*)d_in[12];
    const float* b2  = (const float*)d_in[13];
    const float* g1  = (const float*)d_in[14];
    const float* be1 = (const float*)d_in[15];
    const float* g2  = (const float*)d_in[16];
    const float* be2 = (const float*)d_in[17];
    const float* Wfc = (const float*)d_in[18];
    const float* bfc = (const float*)d_in[19];
    float* out = (float*)d_out;

    float *x, *qkv, *tmp, *scores, *bqkv;
    int *deg, *off, *fill, *eidx;
    __half *xh, *hh;
    __half *wqkv_, *wo_, *w1_, *w2_, *wf_;

    cudaGetSymbolAddress((void**)&x,      g_x);
    cudaGetSymbolAddress((void**)&qkv,    g_qkv);
    cudaGetSymbolAddress((void**)&tmp,    g_tmp);
    cudaGetSymbolAddress((void**)&scores, g_scores);
    cudaGetSymbolAddress((void**)&bqkv,   g_bqkv);
    cudaGetSymbolAddress((void**)&deg,    g_deg);
    cudaGetSymbolAddress((void**)&off,    g_off);
    cudaGetSymbolAddress((void**)&fill,   g_fill);
    cudaGetSymbolAddress((void**)&eidx,   g_eidx);
    cudaGetSymbolAddress((void**)&xh,     g_xh);
    cudaGetSymbolAddress((void**)&hh,     g_hh);
    cudaGetSymbolAddress((void**)&wqkv_,  g_wqkvt);
    cudaGetSymbolAddress((void**)&wo_,    g_wot);
    cudaGetSymbolAddress((void**)&w1_,    g_w1t);
    cudaGetSymbolAddress((void**)&w2_,    g_w2t);
    cudaGetSymbolAddress((void**)&wf_,    g_wfct);

    cudaFuncSetAttribute(f16_gemm,
                         cudaFuncAttributeMaxDynamicSharedMemorySize, GEMM_SMEM);

    cudaMemcpyAsync(x, feats, (size_t)NN * DD * sizeof(float),
                    cudaMemcpyDeviceToDevice, 0);

    // CSR build
    k_zero <<<(NN + 255) / 256, 256>>>(deg, fill);
    k_count<<<(EE + 255) / 256, 256>>>(ei, deg);
    k_scan <<<1, 1024>>>(deg, off);
    k_fill <<<(EE + 255) / 256, 256>>>(ei, off, fill, eidx);

    // Weight conversion (transpose + fp16); QKV weights concatenated per layer
    dim3 tsb(32, 8);
    for (int i = 0; i < LL; i++) {
        size_t oD = (size_t)i * DD * DD, oH = (size_t)i * DD * HIDD;
        size_t oQ = (size_t)i * NQKV * DD;
        transpose_f16_kernel<<<dim3(64, 64),  tsb>>>(Wq + oD, wqkv_ + oQ,                  DD, DD, DD);
        transpose_f16_kernel<<<dim3(64, 64),  tsb>>>(Wk + oD, wqkv_ + oQ + (size_t)DD * DD,     DD, DD, DD);
        transpose_f16_kernel<<<dim3(64, 64),  tsb>>>(Wv + oD, wqkv_ + oQ + (size_t)2 * DD * DD, DD, DD, DD);
        transpose_f16_kernel<<<dim3(64, 64),  tsb>>>(Wo + oD, wo_ + oD, DD, DD, DD);
        transpose_f16_kernel<<<dim3(64, 256), tsb>>>(W1 + oH, w1_ + oH, DD, HIDD, HIDD);
        transpose_f16_kernel<<<dim3(256, 64), tsb>>>(W2 + oH, w2_ + oH, HIDD, DD, DD);
    }
    transpose_f16_kernel<<<dim3(64, 24), tsb>>>(Wfc, wf_, DD, NC, NCPAD);
    pack_bias_kernel<<<(LL * NQKV + 255) / 256, 256>>>(bq, bk, bv, bqkv);

    const size_t nXD = (size_t)NN * DD;
    tofp16_kernel<<<(unsigned)((nXD + 255) / 256), 256>>>(x, xh, nXD);

    dim3 gQ(NQKV / BNg,  NN / BMg);   // (48, 16)
    dim3 gD(DD / BNg,    NN / BMg);   // (16, 16)
    dim3 gH(HIDD / BNg,  NN / BMg);   // (64, 16)
    dim3 gF(NCPAD / BNg, NN / BMg);   // (6, 16)

    for (int i = 0; i < LL; i++) {
        size_t oD = (size_t)i * DD * DD, oH = (size_t)i * DD * HIDD;
        size_t oQ = (size_t)i * NQKV * DD;

        f16_gemm<<<gQ, GEMM_THREADS, GEMM_SMEM>>>(
            xh, wqkv_ + oQ, bqkv + (size_t)i * NQKV, qkv, nullptr, DD, NQKV, 0);

        scores_kernel<<<EE, 256>>>(qkv, ei, scores);
        attn_agg_kernel<<<dim3(NN, HH), 256>>>(scores, qkv, ei, off, eidx, xh);

        f16_gemm<<<gD, GEMM_THREADS, GEMM_SMEM>>>(
            xh, wo_ + oD, bo + (size_t)i * DD, tmp, nullptr, DD, DD, 0);
        add_ln_kernel<<<NN, 256>>>(x, tmp, g1 + (size_t)i * DD, be1 + (size_t)i * DD, xh);

        f16_gemm<<<gH, GEMM_THREADS, GEMM_SMEM>>>(
            xh, w1_ + oH, b1 + (size_t)i * HIDD, nullptr, hh, DD, HIDD, 2);
        f16_gemm<<<gD, GEMM_THREADS, GEMM_SMEM>>>(
            hh, w2_ + oH, b2 + (size_t)i * DD, tmp, nullptr, HIDD, DD, 0);
        add_ln_kernel<<<NN, 256>>>(x, tmp, g2 + (size_t)i * DD, be2 + (size_t)i * DD, xh);
    }

    // logits -> first N*NC floats; then x -> remaining N*D floats
    f16_gemm<<<gF, GEMM_THREADS, GEMM_SMEM>>>(
        xh, wf_, bfc, out, nullptr, DD, NC, 0);
    cudaMemcpyAsync(out + (size_t)NN * NC, x, (size_t)NN * DD * sizeof(float),
                    cudaMemcpyDeviceToDevice, 0);
}

// round 14
// speedup vs baseline: 7.8442x; 1.1970x over previous
#include <cuda_runtime.h>
#include <cuda_fp16.h>
#include <cstdint>
#include <math.h>

// Problem constants
#define NN    4096
#define DD    2048
#define HH    8
#define DHH   256
#define HIDD  8192
#define EE    65536
#define LL    2
#define NC    751
#define NCPAD 768
#define NQKV  6144
#define SCALE 0.0625f   // 1/sqrt(256)

// GEMM tiling: 128x128 tile, 256 threads, 2 CTAs/SM
#define BMg 128
#define BNg 128
#define BKg 32
#define STAGES 4
#define STAGE_BYTES 16384          // A 8K | B 8K
#define GEMM_SMEM (STAGES * STAGE_BYTES)
#define GEMM_THREADS 256

#define ACHUNK 128                 // fused-attention edge chunk

// ---------------- scratch (device globals; no allocation allowed) -------------
__device__ __align__(16) float g_x  [(size_t)NN * DD];
__device__ __align__(16) float g_qkv[(size_t)NN * NQKV];
__device__ __align__(16) float g_tmp[(size_t)NN * DD];
__device__ __align__(16) float g_bqkv[(size_t)LL * NQKV];
__device__ int   g_deg [NN];
__device__ int   g_off [NN + 1];
__device__ int   g_fill[NN];
__device__ int   g_eidx[EE];

// fp16 activations (A operand)
__device__ __align__(16) __half g_xh[(size_t)NN * DD];
__device__ __align__(16) __half g_hh[(size_t)NN * HIDD];

// Transposed fp16 weights ([N][K] layout per layer) — B operand
__device__ __align__(16) __half g_wqkvt[(size_t)LL * NQKV * DD];  // Wq|Wk|Wv concat
__device__ __align__(16) __half g_wot[(size_t)LL * DD * DD];
__device__ __align__(16) __half g_w1t[(size_t)LL * HIDD * DD];
__device__ __align__(16) __half g_w2t[(size_t)LL * DD * HIDD];
__device__ __align__(16) __half g_wfct[(size_t)NCPAD * DD];

// ---------------- PTX helpers (sm_80-level only) ------------------------------
__device__ __forceinline__ uint32_t smem_u32(const void* p) {
    uint32_t a;
    asm("{ .reg .u64 t; cvta.to.shared.u64 t, %1; cvt.u32.u64 %0, t; }"
        : "=r"(a) : "l"(p));
    return a;
}
__device__ __forceinline__ void cp16(uint32_t s, const void* g) {
    asm volatile("cp.async.cg.shared.global [%0], [%1], 16;" :: "r"(s), "l"(g));
}
__device__ __forceinline__ void cp_commit() {
    asm volatile("cp.async.commit_group;" ::: "memory");
}
__device__ __forceinline__ void cp_wait2() {
    asm volatile("cp.async.wait_group 2;" ::: "memory");
}
__device__ __forceinline__ void ldsm4(uint32_t* r, uint32_t a) {
    asm volatile("ldmatrix.sync.aligned.m8n8.x4.shared.b16 {%0,%1,%2,%3}, [%4];"
                 : "=r"(r[0]), "=r"(r[1]), "=r"(r[2]), "=r"(r[3]) : "r"(a));
}
__device__ __forceinline__ void mma16816(float* d, const uint32_t* a, const uint32_t* b) {
    asm volatile("mma.sync.aligned.m16n8k16.row.col.f32.f16.f16.f32 "
                 "{%0,%1,%2,%3}, {%4,%5,%6,%7}, {%8,%9}, {%0,%1,%2,%3};"
                 : "+f"(d[0]), "+f"(d[1]), "+f"(d[2]), "+f"(d[3])
                 : "r"(a[0]), "r"(a[1]), "r"(a[2]), "r"(a[3]),
                   "r"(b[0]), "r"(b[1]));
}
// 64B rows, 4x16B chunks, XOR swizzle keeps ldmatrix reads conflict-free
__device__ __forceinline__ uint32_t tile_addr(uint32_t base, int row, int chunk) {
    return base + (uint32_t)(row * 64) + (uint32_t)((chunk ^ ((row >> 1) & 3)) * 16);
}

// ---------------- conversion kernels -----------------------------------------
__global__ void tofp16_kernel(const float* __restrict__ X,
                              __half* __restrict__ o, size_t n) {
    size_t i = (size_t)blockIdx.x * blockDim.x + threadIdx.x;
    if (i < n) o[i] = __float2half_rn(X[i]);
}

// W [K, Nn] fp32 row-major -> out [Npad, K] fp16 (rows >= Nn zero-filled)
__global__ void transpose_f16_kernel(const float* __restrict__ W,
                                     __half* __restrict__ Wt,
                                     int K, int Nn, int Npad) {
    __shared__ float tile[32][33];
    int k0 = blockIdx.x * 32, n0 = blockIdx.y * 32;
    int tx = threadIdx.x, ty = threadIdx.y;   // 32 x 8
#pragma unroll
    for (int j = 0; j < 32; j += 8) {
        int k = k0 + ty + j, n = n0 + tx;
        tile[ty + j][tx] = (k < K && n < Nn) ? W[(size_t)k * Nn + n] : 0.f;
    }
    __syncthreads();
#pragma unroll
    for (int j = 0; j < 32; j += 8) {
        int n = n0 + ty + j, k = k0 + tx;
        if (n < Npad && k < K)
            Wt[(size_t)n * K + k] = __float2half_rn(tile[tx][ty + j]);
    }
}

// pack bq|bk|bv into one contiguous bias vector per layer
__global__ void pack_bias_kernel(const float* __restrict__ bq,
                                 const float* __restrict__ bk,
                                 const float* __restrict__ bv,
                                 float* __restrict__ o) {
    int i = blockIdx.x * blockDim.x + threadIdx.x;   // 0 .. LL*NQKV-1
    int l = i / NQKV, j = i % NQKV;
    float v;
    if (j < DD)            v = bq[l * DD + j];
    else if (j < 2 * DD)   v = bk[l * DD + (j - DD)];
    else                   v = bv[l * DD + (j - 2 * DD)];
    o[i] = v;
}

// ---------------- fp16 GEMM on mma.sync (HMMA) --------------------------------
// C = A[M,K] @ B^T[Npad,K] + bias
// mode 0: fp32 C; mode 2: relu + fp16 output (Ch)
// grid = (Npad/128, M/128), 256 threads, 2 CTAs/SM. 4-stage cp.async pipeline.
__global__ __launch_bounds__(GEMM_THREADS, 2) void f16_gemm(
    const __half* __restrict__ A, const __half* __restrict__ B,
    const float* __restrict__ bias, float* __restrict__ C,
    __half* __restrict__ Ch,
    int K, int Nn, int mode)
{
    extern __shared__ char smem[];
    const uint32_t sb = smem_u32(smem);
    const int tid  = threadIdx.x;
    const int wid  = tid >> 5, lane = tid & 31;
    const int warpM = wid & 3;          // 4 warps along M (4*32 = 128)
    const int warpN = wid >> 2;         // 2 warps along N (2*64 = 128)
    const int g  = lane >> 3;           // ldmatrix address group
    const int lr = lane & 7;
    const size_t rowBase = (size_t)blockIdx.y * BMg;
    const size_t nBase   = (size_t)blockIdx.x * BNg;
    const int colBase    = blockIdx.x * BNg;
    const int nT = K / BKg;

    float acc[16][4];
#pragma unroll
    for (int i = 0; i < 16; i++)
#pragma unroll
        for (int j = 0; j < 4; j++) acc[i][j] = 0.f;

    // per-stage: 1024 16B chunks (A 512 | B 512), 4/thread
    auto load_stage = [&](int stage, int kt) {
        const uint32_t st = sb + stage * STAGE_BYTES;
        const int k0 = kt * BKg;
#pragma unroll
        for (int i = 0; i < 4; i++) {
            int c = tid + i * GEMM_THREADS;
            int row = (c & 511) >> 2, ch = c & 3;
            uint32_t soff = (uint32_t)((c >> 9) * 8192)
                          + (uint32_t)(row * 64)
                          + (uint32_t)((ch ^ ((row >> 1) & 3)) * 16);
            const __half* gp = (c < 512)
                ? A + (rowBase + row) * (size_t)K + k0 + ch * 8
                : B + (nBase + row) * (size_t)K + k0 + ch * 8;
            cp16(st + soff, gp);
        }
    };

    // prologue: stages 0..2
    load_stage(0, 0); cp_commit();
    load_stage(1, 1); cp_commit();
    load_stage(2, 2); cp_commit();

    const int mOff = warpM * 32;
    const int nOff = warpN * 64;

    for (int kt = 0; kt < nT; kt++) {
        cp_wait2();            // stage kt data arrived (<=2 groups pending)
        __syncthreads();       // all warps done with stage (kt-1)%4 reads
        if (kt + 3 < nT) load_stage((kt + 3) & 3, kt + 3);
        cp_commit();           // always commit to keep group numbering

        const uint32_t st = sb + (kt & 3) * STAGE_BYTES;
        const uint32_t aB = st;
        const uint32_t bB = st + 8192;

#pragma unroll
        for (int ks = 0; ks < 2; ks++) {
            uint32_t ahf[2][4];
#pragma unroll
            for (int mt = 0; mt < 2; mt++) {
                int r = mOff + mt * 16 + lr + (g & 1) * 8;
                int ch = 2 * ks + (g >> 1);
                ldsm4(ahf[mt], tile_addr(aB, r, ch));
            }
#pragma unroll
            for (int p = 0; p < 4; p++) {
                uint32_t bf[4];
                int r = nOff + p * 16 + lr + (g >> 1) * 8;
                int ch = 2 * ks + (g & 1);
                ldsm4(bf, tile_addr(bB, r, ch));
#pragma unroll
                for (int mt = 0; mt < 2; mt++) {
                    mma16816(acc[mt * 8 + 2 * p],     ahf[mt], bf);
                    mma16816(acc[mt * 8 + 2 * p + 1], ahf[mt], bf + 2);
                }
            }
        }
    }

    // epilogue (fragment: rows lane>>2, +8; cols 2*(lane&3), +1)
#pragma unroll
    for (int mt = 0; mt < 2; mt++)
#pragma unroll
        for (int nt = 0; nt < 8; nt++) {
            const float* d = acc[mt * 8 + nt];
            size_t row0 = rowBase + mOff + mt * 16 + (lane >> 2);
            int col0 = colBase + nOff + nt * 8 + (lane & 3) * 2;
            if (col0 >= Nn) continue;
            float b0 = bias[col0];
            float b1 = (col0 + 1 < Nn) ? bias[col0 + 1] : 0.f;
            float v0 = d[0] + b0, v1 = d[1] + b1;
            float v2 = d[2] + b0, v3 = d[3] + b1;
            if (mode == 2) {
                size_t i0 = row0 * (size_t)Nn + col0;
                size_t i2 = (row0 + 8) * (size_t)Nn + col0;
                Ch[i0] = __float2half_rn(fmaxf(v0, 0.f));
                Ch[i2] = __float2half_rn(fmaxf(v2, 0.f));
                if (col0 + 1 < Nn) {
                    Ch[i0 + 1] = __float2half_rn(fmaxf(v1, 0.f));
                    Ch[i2 + 1] = __float2half_rn(fmaxf(v3, 0.f));
                }
            } else {
                C[row0 * (size_t)Nn + col0]       = v0;
                C[(row0 + 8) * (size_t)Nn + col0] = v2;
                if (col0 + 1 < Nn) {
                    C[row0 * (size_t)Nn + col0 + 1]       = v1;
                    C[(row0 + 8) * (size_t)Nn + col0 + 1] = v3;
                }
            }
        }
}

// ---------------- CSR build (group edges by destination c = ei[e][1]) --------
__global__ void k_zero(int* deg, int* fill) {
    int i = blockIdx.x * blockDim.x + threadIdx.x;
    if (i < NN) { deg[i] = 0; fill[i] = 0; }
}
__global__ void k_count(const int* __restrict__ ei, int* deg) {
    int e = blockIdx.x * blockDim.x + threadIdx.x;
    if (e < EE) atomicAdd(&deg[ei[2 * e + 1]], 1);
}
__global__ void k_scan(const int* __restrict__ deg, int* __restrict__ off) {
    __shared__ int s[NN];
    for (int i = threadIdx.x; i < NN; i += blockDim.x) s[i] = deg[i];
    __syncthreads();
    if (threadIdx.x == 0) {
        int acc = 0;
        for (int i = 0; i < NN; i++) { int d = s[i]; s[i] = acc; acc += d; }
    }
    __syncthreads();
    for (int i = threadIdx.x; i < NN; i += blockDim.x) off[i] = s[i];
    if (threadIdx.x == 0) off[NN] = EE;
}
__global__ void k_fill(const int* __restrict__ ei, const int* __restrict__ off,
                       int* fill, int* eidx) {
    int e = blockIdx.x * blockDim.x + threadIdx.x;
    if (e < EE) {
        int c = ei[2 * e + 1];
        int p = atomicAdd(&fill[c], 1);
        eidx[off[c] + p] = e;
    }
}

// ---------------- fused attention: scores + online softmax + aggregation -----
// One block per destination node n. 8 warps = 8 heads. Online softmax over
// edge chunks of ACHUNK (correct for any degree). Writes fp16 agg.
// qkv layout: [NN][6144], q at +0, k at +2048, v at +4096 (fp32).
__global__ __launch_bounds__(256) void attn_fused_kernel(
    const float* __restrict__ qkv,
    const int* __restrict__ ei, const int* __restrict__ off,
    const int* __restrict__ eidx,
    __half* __restrict__ aggh)
{
    const int n = blockIdx.x;
    const int t = threadIdx.x;
    const int h = t >> 5, lane = t & 31;
    const int beg = off[n], end = off[n + 1];

    __shared__ float q_s[DD];                 // 8 KB
    __shared__ float sc[HH][ACHUNK];          // 4 KB: per-head chunk weights
    __shared__ float scale_s[HH];
    __shared__ float l_s[HH];

    if (end <= beg) {
        // no incoming edges: output zeros
#pragma unroll
        for (int hh2 = 0; hh2 < HH; hh2++)
            aggh[(size_t)n * DD + hh2 * DHH + t] = __float2half_rn(0.f);
        return;
    }

    // stage q row
#pragma unroll
    for (int j = 0; j < 8; j++)
        q_s[t + 256 * j] = qkv[(size_t)n * NQKV + t + 256 * j];
    __syncthreads();

    float accv[HH];                            // thread t owns dim t of every head
#pragma unroll
    for (int i = 0; i < HH; i++) accv[i] = 0.f;
    float m_run = -3.4e38f, l_run = 0.f;       // replicated across warp (per head h)

    for (int c0 = beg; c0 < end; c0 += ACHUNK) {
        const int nc = min(ACHUNK, end - c0);

        // --- scores: warp h computes its head's dot for each edge in chunk ---
        float m_chunk = -3.4e38f;
        for (int i = 0; i < nc; i++) {
            int e = eidx[c0 + i];
            int r = ei[2 * e];
            const float* kp = qkv + (size_t)r * NQKV + DD + h * DHH;
            const float* qp = q_s + h * DHH;
            float s = 0.f;
#pragma unroll
            for (int j = 0; j < 8; j++) {
                int d = lane + 32 * j;
                s = fmaf(qp[d], kp[d], s);
            }
#pragma unroll
            for (int o = 16; o; o >>= 1) s += __shfl_xor_sync(0xffffffffu, s, o);
            s *= SCALE;                        // all lanes hold s
            if (lane == 0) sc[h][i] = s;
            m_chunk = fmaxf(m_chunk, s);
        }
        // --- online softmax update (warp-local, per head) ---
        float m_new = fmaxf(m_run, m_chunk);
        float scale = __expf(m_run - m_new);
        float sum = 0.f;
        for (int i = lane; i < nc; i += 32) {
            float w = __expf(sc[h][i] - m_new);
            sc[h][i] = w;
            sum += w;
        }
#pragma unroll
        for (int o = 16; o; o >>= 1) sum += __shfl_xor_sync(0xffffffffu, sum, o);
        l_run = l_run * scale + sum;
        m_run = m_new;
        if (lane == 0) scale_s[h] = scale;
        __syncthreads();                       // sc + scale_s visible to all

        // --- accumulate: thread t handles dim t of all 8 heads ---
#pragma unroll
        for (int hh2 = 0; hh2 < HH; hh2++) accv[hh2] *= scale_s[hh2];
        for (int i = 0; i < nc; i++) {
            int e = eidx[c0 + i];
            int r = ei[2 * e];
            const float* vp = qkv + (size_t)r * NQKV + 2 * DD + t;
#pragma unroll
            for (int hh2 = 0; hh2 < HH; hh2++)
                accv[hh2] = fmaf(sc[hh2][i], vp[hh2 * DHH], accv[hh2]);
        }
        __syncthreads();                       // before next chunk overwrites sc
    }

    if (lane == 0) l_s[h] = l_run;
    __syncthreads();
#pragma unroll
    for (int hh2 = 0; hh2 < HH; hh2++)
        aggh[(size_t)n * DD + hh2 * DHH + t] =
            __float2half_rn(accv[hh2] / l_s[hh2]);
}

// ---------------- residual add + LayerNorm (in place on x; also fp16 out) -----
__global__ __launch_bounds__(256) void add_ln_kernel(
    float* __restrict__ x, const float* __restrict__ x2,
    const float* __restrict__ g, const float* __restrict__ b,
    __half* __restrict__ xh)
{
    int n = blockIdx.x, t = threadIdx.x;
    size_t base = (size_t)n * DD;
    float loc[8];
    float s = 0.f, ss = 0.f;
#pragma unroll
    for (int j = 0; j < 8; j++) {
        int d = t + 256 * j;
        float vv = x[base + d] + x2[base + d];
        loc[j] = vv; s += vv; ss = fmaf(vv, vv, ss);
    }
    __shared__ float sh1[8], sh2[8];
#pragma unroll
    for (int o = 16; o; o >>= 1) {
        s  += __shfl_xor_sync(0xffffffffu, s, o);
        ss += __shfl_xor_sync(0xffffffffu, ss, o);
    }
    int w = t >> 5, lane = t & 31;
    if (lane == 0) { sh1[w] = s; sh2[w] = ss; }
    __syncthreads();
    if (t == 0) {
        float a = 0.f, c2 = 0.f;
        for (int i = 0; i < 8; i++) { a += sh1[i]; c2 += sh2[i]; }
        sh1[0] = a; sh2[0] = c2;
    }
    __syncthreads();
    float mean = sh1[0] * (1.0f / DD);
    float var  = sh2[0] * (1.0f / DD) - mean * mean;
    float inv  = rsqrtf(var + 1e-5f);
#pragma unroll
    for (int j = 0; j < 8; j++) {
        int d = t + 256 * j;
        float o2 = (loc[j] - mean) * inv * g[d] + b[d];
        x[base + d] = o2;
        xh[base + d] = __float2half_rn(o2);
    }
}

// ---------------- host launcher ----------------------------------------------
extern "C" void kernel_launch(void* const* d_in, const int* in_sizes, int n_in,
                              void* d_out, int out_size)
{
    const float* feats = (const float*)d_in[0];
    const int*   ei    = (const int*)  d_in[1];
    const float* Wq  = (const float*)d_in[2];
    const float* bq  = (const float*)d_in[3];
    const float* Wk  = (const float*)d_in[4];
    const float* bk  = (const float*)d_in[5];
    const float* Wv  = (const float*)d_in[6];
    const float* bv  = (const float*)d_in[7];
    const float* Wo  = (const float*)d_in[8];
    const float* bo  = (const float*)d_in[9];
    const float* W1  = (const float*)d_in[10];
    const float* b1  = (const float*)d_in[11];
    const float* W2  = (const float*)d_in[12];
    const float* b2  = (const float*)d_in[13];
    const float* g1  = (const float*)d_in[14];
    const float* be1 = (const float*)d_in[15];
    const float* g2  = (const float*)d_in[16];
    const float* be2 = (const float*)d_in[17];
    const float* Wfc = (const float*)d_in[18];
    const float* bfc = (const float*)d_in[19];
    float* out = (float*)d_out;

    float *x, *qkv, *tmp, *bqkv;
    int *deg, *off, *fill, *eidx;
    __half *xh, *hh;
    __half *wqkv_, *wo_, *w1_, *w2_, *wf_;

    cudaGetSymbolAddress((void**)&x,      g_x);
    cudaGetSymbolAddress((void**)&qkv,    g_qkv);
    cudaGetSymbolAddress((void**)&tmp,    g_tmp);
    cudaGetSymbolAddress((void**)&bqkv,   g_bqkv);
    cudaGetSymbolAddress((void**)&deg,    g_deg);
    cudaGetSymbolAddress((void**)&off,    g_off);
    cudaGetSymbolAddress((void**)&fill,   g_fill);
    cudaGetSymbolAddress((void**)&eidx,   g_eidx);
    cudaGetSymbolAddress((void**)&xh,     g_xh);
    cudaGetSymbolAddress((void**)&hh,     g_hh);
    cudaGetSymbolAddress((void**)&wqkv_,  g_wqkvt);
    cudaGetSymbolAddress((void**)&wo_,    g_wot);
    cudaGetSymbolAddress((void**)&w1_,    g_w1t);
    cudaGetSymbolAddress((void**)&w2_,    g_w2t);
    cudaGetSymbolAddress((void**)&wf_,    g_wfct);

    cudaFuncSetAttribute(f16_gemm,
                         cudaFuncAttributeMaxDynamicSharedMemorySize, GEMM_SMEM);

    cudaMemcpyAsync(x, feats, (size_t)NN * DD * sizeof(float),
                    cudaMemcpyDeviceToDevice, 0);

    // CSR build
    k_zero <<<(NN + 255) / 256, 256>>>(deg, fill);
    k_count<<<(EE + 255) / 256, 256>>>(ei, deg);
    k_scan <<<1, 1024>>>(deg, off);
    k_fill <<<(EE + 255) / 256, 256>>>(ei, off, fill, eidx);

    // Weight conversion (transpose + fp16); QKV weights concatenated per layer
    dim3 tsb(32, 8);
    for (int i = 0; i < LL; i++) {
        size_t oD = (size_t)i * DD * DD, oH = (size_t)i * DD * HIDD;
        size_t oQ = (size_t)i * NQKV * DD;
        transpose_f16_kernel<<<dim3(64, 64),  tsb>>>(Wq + oD, wqkv_ + oQ,                  DD, DD, DD);
        transpose_f16_kernel<<<dim3(64, 64),  tsb>>>(Wk + oD, wqkv_ + oQ + (size_t)DD * DD,     DD, DD, DD);
        transpose_f16_kernel<<<dim3(64, 64),  tsb>>>(Wv + oD, wqkv_ + oQ + (size_t)2 * DD * DD, DD, DD, DD);
        transpose_f16_kernel<<<dim3(64, 64),  tsb>>>(Wo + oD, wo_ + oD, DD, DD, DD);
        transpose_f16_kernel<<<dim3(64, 256), tsb>>>(W1 + oH, w1_ + oH, DD, HIDD, HIDD);
        transpose_f16_kernel<<<dim3(256, 64), tsb>>>(W2 + oH, w2_ + oH, HIDD, DD, DD);
    }
    transpose_f16_kernel<<<dim3(64, 24), tsb>>>(Wfc, wf_, DD, NC, NCPAD);
    pack_bias_kernel<<<(LL * NQKV + 255) / 256, 256>>>(bq, bk, bv, bqkv);

    const size_t nXD = (size_t)NN * DD;
    tofp16_kernel<<<(unsigned)((nXD + 255) / 256), 256>>>(x, xh, nXD);

    dim3 gQ(NQKV / BNg,  NN / BMg);   // (48, 32)
    dim3 gD(DD / BNg,    NN / BMg);   // (16, 32)
    dim3 gH(HIDD / BNg,  NN / BMg);   // (64, 32)
    dim3 gF(NCPAD / BNg, NN / BMg);   // (6, 32)

    for (int i = 0; i < LL; i++) {
        size_t oD = (size_t)i * DD * DD, oH = (size_t)i * DD * HIDD;
        size_t oQ = (size_t)i * NQKV * DD;

        f16_gemm<<<gQ, GEMM_THREADS, GEMM_SMEM>>>(
            xh, wqkv_ + oQ, bqkv + (size_t)i * NQKV, qkv, nullptr, DD, NQKV, 0);

        attn_fused_kernel<<<NN, 256>>>(qkv, ei, off, eidx, xh);

        f16_gemm<<<gD, GEMM_THREADS, GEMM_SMEM>>>(
            xh, wo_ + oD, bo + (size_t)i * DD, tmp, nullptr, DD, DD, 0);
        add_ln_kernel<<<NN, 256>>>(x, tmp, g1 + (size_t)i * DD, be1 + (size_t)i * DD, xh);

        f16_gemm<<<gH, GEMM_THREADS, GEMM_SMEM>>>(
            xh, w1_ + oH, b1 + (size_t)i * HIDD, nullptr, hh, DD, HIDD, 2);
        f16_gemm<<<gD, GEMM_THREADS, GEMM_SMEM>>>(
            hh, w2_ + oH, b2 + (size_t)i * DD, tmp, nullptr, HIDD, DD, 0);
        add_ln_kernel<<<NN, 256>>>(x, tmp, g2 + (size_t)i * DD, be2 + (size_t)i * DD, xh);
    }

    // logits -> first N*NC floats; then x -> remaining N*D floats
    f16_gemm<<<gF, GEMM_THREADS, GEMM_SMEM>>>(
        xh, wf_, bfc, out, nullptr, DD, NC, 0);
    cudaMemcpyAsync(out + (size_t)NN * NC, x, (size_t)NN * DD * sizeof(float),
                    cudaMemcpyDeviceToDevice, 0);
}

// round 17
// speedup vs baseline: 8.2354x; 1.0499x over previous
#include <cuda_runtime.h>
#include <cuda_fp16.h>
#include <cstdint>
#include <math.h>

// Problem constants
#define NN    4096
#define DD    2048
#define HH    8
#define DHH   256
#define HIDD  8192
#define EE    65536
#define LL    2
#define NC    751
#define NCPAD 768
#define NQKV  6144
#define SCALE 0.0625f   // 1/sqrt(256)

// GEMM tiling: 128x128 tile, 256 threads, 2 CTAs/SM
#define BMg 128
#define BNg 128
#define BKg 32
#define STAGES 4
#define STAGE_BYTES 16384          // A 8K | B 8K
#define GEMM_SMEM (STAGES * STAGE_BYTES)
#define GEMM_THREADS 256

#define ACHUNK 128                 // fused-attention edge chunk

// ---------------- scratch (device globals; no allocation allowed) -------------
__device__ __align__(16) float g_x  [(size_t)NN * DD];
__device__ __align__(16) float g_tmp[(size_t)NN * DD];
__device__ __align__(16) float g_bqkv[(size_t)LL * NQKV];
__device__ int   g_deg [NN];
__device__ int   g_off [NN + 1];
__device__ int   g_fill[NN];
__device__ int   g_src [EE];

// fp16 activations
__device__ __align__(16) __half g_qkvh[(size_t)NN * NQKV];
__device__ __align__(16) __half g_xh[(size_t)NN * DD];
__device__ __align__(16) __half g_hh[(size_t)NN * HIDD];

// Transposed fp16 weights ([N][K] layout per layer) — B operand
__device__ __align__(16) __half g_wqkvt[(size_t)LL * NQKV * DD];  // Wq|Wk|Wv concat
__device__ __align__(16) __half g_wot[(size_t)LL * DD * DD];
__device__ __align__(16) __half g_w1t[(size_t)LL * HIDD * DD];
__device__ __align__(16) __half g_w2t[(size_t)LL * DD * HIDD];
__device__ __align__(16) __half g_wfct[(size_t)NCPAD * DD];

// ---------------- PTX helpers (sm_80-level only) ------------------------------
__device__ __forceinline__ uint32_t smem_u32(const void* p) {
    uint32_t a;
    asm("{ .reg .u64 t; cvta.to.shared.u64 t, %1; cvt.u32.u64 %0, t; }"
        : "=r"(a) : "l"(p));
    return a;
}
__device__ __forceinline__ void cp16(uint32_t s, const void* g) {
    asm volatile("cp.async.cg.shared.global [%0], [%1], 16;" :: "r"(s), "l"(g));
}
__device__ __forceinline__ void cp_commit() {
    asm volatile("cp.async.commit_group;" ::: "memory");
}
__device__ __forceinline__ void cp_wait2() {
    asm volatile("cp.async.wait_group 2;" ::: "memory");
}
__device__ __forceinline__ void ldsm4(uint32_t* r, uint32_t a) {
    asm volatile("ldmatrix.sync.aligned.m8n8.x4.shared.b16 {%0,%1,%2,%3}, [%4];"
                 : "=r"(r[0]), "=r"(r[1]), "=r"(r[2]), "=r"(r[3]) : "r"(a));
}
__device__ __forceinline__ void mma16816(float* d, const uint32_t* a, const uint32_t* b) {
    asm volatile("mma.sync.aligned.m16n8k16.row.col.f32.f16.f16.f32 "
                 "{%0,%1,%2,%3}, {%4,%5,%6,%7}, {%8,%9}, {%0,%1,%2,%3};"
                 : "+f"(d[0]), "+f"(d[1]), "+f"(d[2]), "+f"(d[3])
                 : "r"(a[0]), "r"(a[1]), "r"(a[2]), "r"(a[3]),
                   "r"(b[0]), "r"(b[1]));
}
// 64B rows, 4x16B chunks, XOR swizzle keeps ldmatrix reads conflict-free
__device__ __forceinline__ uint32_t tile_addr(uint32_t base, int row, int chunk) {
    return base + (uint32_t)(row * 64) + (uint32_t)((chunk ^ ((row >> 1) & 3)) * 16);
}

// ---------------- conversion kernels -----------------------------------------
__global__ void tofp16_kernel(const float* __restrict__ X,
                              __half* __restrict__ o, size_t n) {
    size_t i = (size_t)blockIdx.x * blockDim.x + threadIdx.x;
    if (i < n) o[i] = __float2half_rn(X[i]);
}

// generic 32x32 transpose tile body (all dims divisible by 32 here)
__device__ __forceinline__ void transpose_tile(const float* __restrict__ W,
                                               __half* __restrict__ Wt,
                                               int K, int Nn, int k0, int n0,
                                               int tx, int ty) {
    __shared__ float tile[32][33];
#pragma unroll
    for (int j = 0; j < 32; j += 8)
        tile[ty + j][tx] = W[(size_t)(k0 + ty + j) * Nn + n0 + tx];
    __syncthreads();
#pragma unroll
    for (int j = 0; j < 32; j += 8)
        Wt[(size_t)(n0 + ty + j) * K + k0 + tx] = __float2half_rn(tile[tx][ty + j]);
}

// 8 D x D matrices: z = layer*4 + {q,k,v,o}
__global__ void transpose_dd8_kernel(const float* __restrict__ Wq,
                                     const float* __restrict__ Wk,
                                     const float* __restrict__ Wv,
                                     const float* __restrict__ Wo,
                                     __half* __restrict__ wqkv,
                                     __half* __restrict__ wo) {
    int z = blockIdx.z, l = z >> 2, ty_ = z & 3;
    size_t oD = (size_t)l * DD * DD;
    size_t oQ = (size_t)l * NQKV * DD;
    const float* W; __half* Wt;
    if (ty_ == 0)      { W = Wq + oD; Wt = wqkv + oQ; }
    else if (ty_ == 1) { W = Wk + oD; Wt = wqkv + oQ + (size_t)DD * DD; }
    else if (ty_ == 2) { W = Wv + oD; Wt = wqkv + oQ + (size_t)2 * DD * DD; }
    else               { W = Wo + oD; Wt = wo + oD; }
    transpose_tile(W, Wt, DD, DD, blockIdx.x * 32, blockIdx.y * 32,
                   threadIdx.x, threadIdx.y);
}

// W1 (z=0,1) and W2 (z=2,3); grid (64, 256, 4)
__global__ void transpose_ffn_kernel(const float* __restrict__ W1,
                                     const float* __restrict__ W2,
                                     __half* __restrict__ w1t,
                                     __half* __restrict__ w2t) {
    int z = blockIdx.z;
    if (z < 2) {
        size_t o = (size_t)z * DD * HIDD;
        transpose_tile(W1 + o, w1t + o, DD, HIDD,
                       blockIdx.x * 32, blockIdx.y * 32, threadIdx.x, threadIdx.y);
    } else {
        size_t o = (size_t)(z - 2) * HIDD * DD;
        transpose_tile(W2 + o, w2t + o, HIDD, DD,
                       blockIdx.y * 32, blockIdx.x * 32, threadIdx.x, threadIdx.y);
    }
}

// W [K, Nn] fp32 row-major -> out [Npad, K] fp16 (rows >= Nn zero-filled)
__global__ void transpose_f16_kernel(const float* __restrict__ W,
                                     __half* __restrict__ Wt,
                                     int K, int Nn, int Npad) {
    __shared__ float tile[32][33];
    int k0 = blockIdx.x * 32, n0 = blockIdx.y * 32;
    int tx = threadIdx.x, ty = threadIdx.y;   // 32 x 8
#pragma unroll
    for (int j = 0; j < 32; j += 8) {
        int k = k0 + ty + j, n = n0 + tx;
        tile[ty + j][tx] = (k < K && n < Nn) ? W[(size_t)k * Nn + n] : 0.f;
    }
    __syncthreads();
#pragma unroll
    for (int j = 0; j < 32; j += 8) {
        int n = n0 + ty + j, k = k0 + tx;
        if (n < Npad && k < K)
            Wt[(size_t)n * K + k] = __float2half_rn(tile[tx][ty + j]);
    }
}

// pack bq|bk|bv into one contiguous bias vector per layer
__global__ void pack_bias_kernel(const float* __restrict__ bq,
                                 const float* __restrict__ bk,
                                 const float* __restrict__ bv,
                                 float* __restrict__ o) {
    int i = blockIdx.x * blockDim.x + threadIdx.x;   // 0 .. LL*NQKV-1
    int l = i / NQKV, j = i % NQKV;
    float v;
    if (j < DD)            v = bq[l * DD + j];
    else if (j < 2 * DD)   v = bk[l * DD + (j - DD)];
    else                   v = bv[l * DD + (j - 2 * DD)];
    o[i] = v;
}

// ---------------- fp16 GEMM on mma.sync (HMMA) --------------------------------
// C = A[M,K] @ B^T[Npad,K] + bias
// mode 0: fp32 C; mode 2: relu + fp16 out (Ch); mode 3: fp16 out (Ch)
// grid = (Npad/128, M/128), 256 threads, 2 CTAs/SM. 4-stage cp.async pipeline.
__global__ __launch_bounds__(GEMM_THREADS, 2) void f16_gemm(
    const __half* __restrict__ A, const __half* __restrict__ B,
    const float* __restrict__ bias, float* __restrict__ C,
    __half* __restrict__ Ch,
    int K, int Nn, int mode)
{
    extern __shared__ char smem[];
    const uint32_t sb = smem_u32(smem);
    const int tid  = threadIdx.x;
    const int wid  = tid >> 5, lane = tid & 31;
    const int warpM = wid & 3;          // 4 warps along M (4*32 = 128)
    const int warpN = wid >> 2;         // 2 warps along N (2*64 = 128)
    const int g  = lane >> 3;           // ldmatrix address group
    const int lr = lane & 7;
    const size_t rowBase = (size_t)blockIdx.y * BMg;
    const size_t nBase   = (size_t)blockIdx.x * BNg;
    const int colBase    = blockIdx.x * BNg;
    const int nT = K / BKg;

    float acc[16][4];
#pragma unroll
    for (int i = 0; i < 16; i++)
#pragma unroll
        for (int j = 0; j < 4; j++) acc[i][j] = 0.f;

    // per-stage: 1024 16B chunks (A 512 | B 512), 4/thread
    auto load_stage = [&](int stage, int kt) {
        const uint32_t st = sb + stage * STAGE_BYTES;
        const int k0 = kt * BKg;
#pragma unroll
        for (int i = 0; i < 4; i++) {
            int c = tid + i * GEMM_THREADS;
            int row = (c & 511) >> 2, ch = c & 3;
            uint32_t soff = (uint32_t)((c >> 9) * 8192)
                          + (uint32_t)(row * 64)
                          + (uint32_t)((ch ^ ((row >> 1) & 3)) * 16);
            const __half* gp = (c < 512)
                ? A + (rowBase + row) * (size_t)K + k0 + ch * 8
                : B + (nBase + row) * (size_t)K + k0 + ch * 8;
            cp16(st + soff, gp);
        }
    };

    // prologue: stages 0..2
    load_stage(0, 0); cp_commit();
    load_stage(1, 1); cp_commit();
    load_stage(2, 2); cp_commit();

    const int mOff = warpM * 32;
    const int nOff = warpN * 64;

    for (int kt = 0; kt < nT; kt++) {
        cp_wait2();            // stage kt data arrived (<=2 groups pending)
        __syncthreads();       // all warps done with stage (kt-1)%4 reads
        if (kt + 3 < nT) load_stage((kt + 3) & 3, kt + 3);
        cp_commit();           // always commit to keep group numbering

        const uint32_t st = sb + (kt & 3) * STAGE_BYTES;
        const uint32_t aB = st;
        const uint32_t bB = st + 8192;

#pragma unroll
        for (int ks = 0; ks < 2; ks++) {
            uint32_t ahf[2][4];
#pragma unroll
            for (int mt = 0; mt < 2; mt++) {
                int r = mOff + mt * 16 + lr + (g & 1) * 8;
                int ch = 2 * ks + (g >> 1);
                ldsm4(ahf[mt], tile_addr(aB, r, ch));
            }
#pragma unroll
            for (int p = 0; p < 4; p++) {
                uint32_t bf[4];
                int r = nOff + p * 16 + lr + (g >> 1) * 8;
                int ch = 2 * ks + (g & 1);
                ldsm4(bf, tile_addr(bB, r, ch));
#pragma unroll
                for (int mt = 0; mt < 2; mt++) {
                    mma16816(acc[mt * 8 + 2 * p],     ahf[mt], bf);
                    mma16816(acc[mt * 8 + 2 * p + 1], ahf[mt], bf + 2);
                }
            }
        }
    }

    // epilogue (fragment: rows lane>>2, +8; cols 2*(lane&3), +1)
    const bool relu = (mode == 2);
#pragma unroll
    for (int mt = 0; mt < 2; mt++)
#pragma unroll
        for (int nt = 0; nt < 8; nt++) {
            const float* d = acc[mt * 8 + nt];
            size_t row0 = rowBase + mOff + mt * 16 + (lane >> 2);
            int col0 = colBase + nOff + nt * 8 + (lane & 3) * 2;
            if (col0 >= Nn) continue;
            float b0 = bias[col0];
            float b1 = (col0 + 1 < Nn) ? bias[col0 + 1] : 0.f;
            float v0 = d[0] + b0, v1 = d[1] + b1;
            float v2 = d[2] + b0, v3 = d[3] + b1;
            if (mode) {
                if (relu) {
                    v0 = fmaxf(v0, 0.f); v1 = fmaxf(v1, 0.f);
                    v2 = fmaxf(v2, 0.f); v3 = fmaxf(v3, 0.f);
                }
                size_t i0 = row0 * (size_t)Nn + col0;
                size_t i2 = (row0 + 8) * (size_t)Nn + col0;
                Ch[i0] = __float2half_rn(v0);
                Ch[i2] = __float2half_rn(v2);
                if (col0 + 1 < Nn) {
                    Ch[i0 + 1] = __float2half_rn(v1);
                    Ch[i2 + 1] = __float2half_rn(v3);
                }
            } else {
                C[row0 * (size_t)Nn + col0]       = v0;
                C[(row0 + 8) * (size_t)Nn + col0] = v2;
                if (col0 + 1 < Nn) {
                    C[row0 * (size_t)Nn + col0 + 1]       = v1;
                    C[(row0 + 8) * (size_t)Nn + col0 + 1] = v3;
                }
            }
        }
}

// ---------------- CSR build (group edges by destination c = ei[e][1]) --------
__global__ void k_zero(int* deg, int* fill) {
    int i = blockIdx.x * blockDim.x + threadIdx.x;
    if (i < NN) { deg[i] = 0; fill[i] = 0; }
}
__global__ void k_count(const int* __restrict__ ei, int* deg) {
    int e = blockIdx.x * blockDim.x + threadIdx.x;
    if (e < EE) atomicAdd(&deg[ei[2 * e + 1]], 1);
}
__global__ void k_scan(const int* __restrict__ deg, int* __restrict__ off) {
    __shared__ int s[NN];
    for (int i = threadIdx.x; i < NN; i += blockDim.x) s[i] = deg[i];
    __syncthreads();
    if (threadIdx.x == 0) {
        int acc = 0;
        for (int i = 0; i < NN; i++) { int d = s[i]; s[i] = acc; acc += d; }
    }
    __syncthreads();
    for (int i = threadIdx.x; i < NN; i += blockDim.x) off[i] = s[i];
    if (threadIdx.x == 0) off[NN] = EE;
}
// store SOURCE node id directly (attention only ever needs k/v of the source)
__global__ void k_fill(const int* __restrict__ ei, const int* __restrict__ off,
                       int* fill, int* srcs) {
    int e = blockIdx.x * blockDim.x + threadIdx.x;
    if (e < EE) {
        int r = ei[2 * e], c = ei[2 * e + 1];
        int p = atomicAdd(&fill[c], 1);
        srcs[off[c] + p] = r;
    }
}

// ---------------- fused attention (fp16 qkv, fp32 math) ----------------------
// One block per destination node n. 8 warps = 8 heads. Online softmax over
// edge chunks. qkv layout: [NN][6144] fp16, q at +0, k at +2048, v at +4096.
__global__ __launch_bounds__(256) void attn_fused_kernel(
    const __half* __restrict__ qkv,
    const int* __restrict__ srcs, const int* __restrict__ off,
    __half* __restrict__ aggh)
{
    const int n = blockIdx.x;
    const int t = threadIdx.x;
    const int h = t >> 5, lane = t & 31;
    const int beg = off[n], end = off[n + 1];

    __shared__ __align__(16) float q_s[DD];   // 8 KB
    __shared__ float sc[HH][ACHUNK];          // 4 KB
    __shared__ int   src_s[ACHUNK];
    __shared__ float scale_s[HH];
    __shared__ float l_s[HH];

    if (end <= beg) {
#pragma unroll
        for (int hh2 = 0; hh2 < HH; hh2++)
            aggh[(size_t)n * DD + hh2 * DHH + t] = __float2half_rn(0.f);
        return;
    }

    // stage q row (fp16 -> fp32)
    {
        const __half2* qg = (const __half2*)(qkv + (size_t)n * NQKV);
        float2* qs = (float2*)q_s;
#pragma unroll
        for (int j = 0; j < 4; j++)
            qs[t + 256 * j] = __half22float2(qg[t + 256 * j]);
    }
    __syncthreads();

    float accv[HH];
#pragma unroll
    for (int i = 0; i < HH; i++) accv[i] = 0.f;
    float m_run = -3.4e38f, l_run = 0.f;

    for (int c0 = beg; c0 < end; c0 += ACHUNK) {
        const int nc = min(ACHUNK, end - c0);

        // stage source ids
        for (int i = t; i < nc; i += 256) src_s[i] = srcs[c0 + i];
        __syncthreads();

        // --- scores: warp h computes its head's dot for each edge ---
        const float2* qh = (const float2*)(q_s + h * DHH);   // 128 float2
        float m_chunk = -3.4e38f;
        for (int i = 0; i < nc; i++) {
            const __half2* kp2 = (const __half2*)
                (qkv + (size_t)src_s[i] * NQKV + DD + h * DHH);
            float s = 0.f;
#pragma unroll
            for (int j = 0; j < 4; j++) {
                float2 qf = qh[lane + 32 * j];
                float2 kf = __half22float2(kp2[lane + 32 * j]);
                s = fmaf(qf.x, kf.x, s);
                s = fmaf(qf.y, kf.y, s);
            }
#pragma unroll
            for (int o = 16; o; o >>= 1) s += __shfl_xor_sync(0xffffffffu, s, o);
            s *= SCALE;
            if (lane == 0) sc[h][i] = s;
            m_chunk = fmaxf(m_chunk, s);
        }
        // --- online softmax update (warp-local, per head) ---
        float m_new = fmaxf(m_run, m_chunk);
        float scale = __expf(m_run - m_new);
        float sum = 0.f;
        for (int i = lane; i < nc; i += 32) {
            float w = __expf(sc[h][i] - m_new);
            sc[h][i] = w;
            sum += w;
        }
#pragma unroll
        for (int o = 16; o; o >>= 1) sum += __shfl_xor_sync(0xffffffffu, sum, o);
        l_run = l_run * scale + sum;
        m_run = m_new;
        if (lane == 0) scale_s[h] = scale;
        __syncthreads();                       // sc + scale_s visible to all

        // --- accumulate: thread t handles dim t of all 8 heads ---
#pragma unroll
        for (int hh2 = 0; hh2 < HH; hh2++) accv[hh2] *= scale_s[hh2];
        for (int i = 0; i < nc; i++) {
            const __half* vp = qkv + (size_t)src_s[i] * NQKV + 2 * DD + t;
#pragma unroll
            for (int hh2 = 0; hh2 < HH; hh2++)
                accv[hh2] = fmaf(sc[hh2][i], __half2float(vp[hh2 * DHH]), accv[hh2]);
        }
        __syncthreads();                       // before next chunk overwrites sc/src_s
    }

    if (lane == 0) l_s[h] = l_run;
    __syncthreads();
#pragma unroll
    for (int hh2 = 0; hh2 < HH; hh2++)
        aggh[(size_t)n * DD + hh2 * DHH + t] =
            __float2half_rn(accv[hh2] / l_s[hh2]);
}

// ---------------- residual add + LayerNorm (in place on x; also fp16 out) -----
__global__ __launch_bounds__(256) void add_ln_kernel(
    float* __restrict__ x, const float* __restrict__ x2,
    const float* __restrict__ g, const float* __restrict__ b,
    __half* __restrict__ xh)
{
    int n = blockIdx.x, t = threadIdx.x;
    size_t base = (size_t)n * DD;
    float loc[8];
    float s = 0.f, ss = 0.f;
#pragma unroll
    for (int j = 0; j < 8; j++) {
        int d = t + 256 * j;
        float vv = x[base + d] + x2[base + d];
        loc[j] = vv; s += vv; ss = fmaf(vv, vv, ss);
    }
    __shared__ float sh1[8], sh2[8];
#pragma unroll
    for (int o = 16; o; o >>= 1) {
        s  += __shfl_xor_sync(0xffffffffu, s, o);
        ss += __shfl_xor_sync(0xffffffffu, ss, o);
    }
    int w = t >> 5, lane = t & 31;
    if (lane == 0) { sh1[w] = s; sh2[w] = ss; }
    __syncthreads();
    if (t == 0) {
        float a = 0.f, c2 = 0.f;
        for (int i = 0; i < 8; i++) { a += sh1[i]; c2 += sh2[i]; }
        sh1[0] = a; sh2[0] = c2;
    }
    __syncthreads();
    float mean = sh1[0] * (1.0f / DD);
    float var  = sh2[0] * (1.0f / DD) - mean * mean;
    float inv  = rsqrtf(var + 1e-5f);
#pragma unroll
    for (int j = 0; j < 8; j++) {
        int d = t + 256 * j;
        float o2 = (loc[j] - mean) * inv * g[d] + b[d];
        x[base + d] = o2;
        xh[base + d] = __float2half_rn(o2);
    }
}

// ---------------- host launcher ----------------------------------------------
extern "C" void kernel_launch(void* const* d_in, const int* in_sizes, int n_in,
                              void* d_out, int out_size)
{
    const float* feats = (const float*)d_in[0];
    const int*   ei    = (const int*)  d_in[1];
    const float* Wq  = (const float*)d_in[2];
    const float* bq  = (const float*)d_in[3];
    const float* Wk  = (const float*)d_in[4];
    const float* bk  = (const float*)d_in[5];
    const float* Wv  = (const float*)d_in[6];
    const float* bv  = (const float*)d_in[7];
    const float* Wo  = (const float*)d_in[8];
    const float* bo  = (const float*)d_in[9];
    const float* W1  = (const float*)d_in[10];
    const float* b1  = (const float*)d_in[11];
    const float* W2  = (const float*)d_in[12];
    const float* b2  = (const float*)d_in[13];
    const float* g1  = (const float*)d_in[14];
    const float* be1 = (const float*)d_in[15];
    const float* g2  = (const float*)d_in[16];
    const float* be2 = (const float*)d_in[17];
    const float* Wfc = (const float*)d_in[18];
    const float* bfc = (const float*)d_in[19];
    float* out = (float*)d_out;

    float *x, *tmp, *bqkv;
    int *deg, *off, *fill, *srcs;
    __half *qkvh, *xh, *hh;
    __half *wqkv_, *wo_, *w1_, *w2_, *wf_;

    cudaGetSymbolAddress((void**)&x,      g_x);
    cudaGetSymbolAddress((void**)&tmp,    g_tmp);
    cudaGetSymbolAddress((void**)&bqkv,   g_bqkv);
    cudaGetSymbolAddress((void**)&deg,    g_deg);
    cudaGetSymbolAddress((void**)&off,    g_off);
    cudaGetSymbolAddress((void**)&fill,   g_fill);
    cudaGetSymbolAddress((void**)&srcs,   g_src);
    cudaGetSymbolAddress((void**)&qkvh,   g_qkvh);
    cudaGetSymbolAddress((void**)&xh,     g_xh);
    cudaGetSymbolAddress((void**)&hh,     g_hh);
    cudaGetSymbolAddress((void**)&wqkv_,  g_wqkvt);
    cudaGetSymbolAddress((void**)&wo_,    g_wot);
    cudaGetSymbolAddress((void**)&w1_,    g_w1t);
    cudaGetSymbolAddress((void**)&w2_,    g_w2t);
    cudaGetSymbolAddress((void**)&wf_,    g_wfct);

    cudaFuncSetAttribute(f16_gemm,
                         cudaFuncAttributeMaxDynamicSharedMemorySize, GEMM_SMEM);

    cudaMemcpyAsync(x, feats, (size_t)NN * DD * sizeof(float),
                    cudaMemcpyDeviceToDevice, 0);

    // CSR build
    k_zero <<<(NN + 255) / 256, 256>>>(deg, fill);
    k_count<<<(EE + 255) / 256, 256>>>(ei, deg);
    k_scan <<<1, 1024>>>(deg, off);
    k_fill <<<(EE + 255) / 256, 256>>>(ei, off, fill, srcs);

    // Weight conversion (batched transposes + fp16)
    dim3 tsb(32, 8);
    transpose_dd8_kernel<<<dim3(64, 64, 8), tsb>>>(Wq, Wk, Wv, Wo, wqkv_, wo_);
    transpose_ffn_kernel<<<dim3(64, 256, 4), tsb>>>(W1, W2, w1_, w2_);
    transpose_f16_kernel<<<dim3(64, 24), tsb>>>(Wfc, wf_, DD, NC, NCPAD);
    pack_bias_kernel<<<(LL * NQKV + 255) / 256, 256>>>(bq, bk, bv, bqkv);

    const size_t nXD = (size_t)NN * DD;
    tofp16_kernel<<<(unsigned)((nXD + 255) / 256), 256>>>(x, xh, nXD);

    dim3 gQ(NQKV / BNg,  NN / BMg);   // (48, 32)
    dim3 gD(DD / BNg,    NN / BMg);   // (16, 32)
    dim3 gH(HIDD / BNg,  NN / BMg);   // (64, 32)
    dim3 gF(NCPAD / BNg, NN / BMg);   // (6, 32)

    for (int i = 0; i < LL; i++) {
        size_t oD = (size_t)i * DD * DD, oH = (size_t)i * DD * HIDD;
        size_t oQ = (size_t)i * NQKV * DD;

        // QKV projection, fp16 output (mode 3)
        f16_gemm<<<gQ, GEMM_THREADS, GEMM_SMEM>>>(
            xh, wqkv_ + oQ, bqkv + (size_t)i * NQKV, nullptr, qkvh, DD, NQKV, 3);

        attn_fused_kernel<<<NN, 256>>>(qkvh, srcs, off, xh);

        f16_gemm<<<gD, GEMM_THREADS, GEMM_SMEM>>>(
            xh, wo_ + oD, bo + (size_t)i * DD, tmp, nullptr, DD, DD, 0);
        add_ln_kernel<<<NN, 256>>>(x, tmp, g1 + (size_t)i * DD, be1 + (size_t)i * DD, xh);

        f16_gemm<<<gH, GEMM_THREADS, GEMM_SMEM>>>(
            xh, w1_ + oH, b1 + (size_t)i * HIDD, nullptr, hh, DD, HIDD, 2);
        f16_gemm<<<gD, GEMM_THREADS, GEMM_SMEM>>>(
            hh, w2_ + oH, b2 + (size_t)i * DD, tmp, nullptr, HIDD, DD, 0);
        add_ln_kernel<<<NN, 256>>>(x, tmp, g2 + (size_t)i * DD, be2 + (size_t)i * DD, xh);
    }

    // logits -> first N*NC floats; then x -> remaining N*D floats
    f16_gemm<<<gF, GEMM_THREADS, GEMM_SMEM>>>(
        xh, wf_, bfc, out, nullptr, DD, NC, 0);
    cudaMemcpyAsync(out + (size_t)NN * NC, x, (size_t)NN * DD * sizeof(float),
                    cudaMemcpyDeviceToDevice, 0);
}